// round 6
// baseline (speedup 1.0000x reference)
#include <cuda_runtime.h>
#include <cuda_bf16.h>
#include <math.h>
#include <stdint.h>

#define BB 64
#define SS 512
#define II 1024
#define HH 1024

#define NCTA_SCAN 128            // 128 CTAs x 8 cols each
#define NTHR_SCAN 256
#define SCAN_THREADS (NCTA_SCAN * NTHR_SCAN)
#define UPITCH 1032              // bf16 elems; 2064B rows -> conflict-free ldmatrix

// ---------------------------------------------------------------------------
// Device globals (no allocation allowed anywhere)
// ---------------------------------------------------------------------------
__device__ float g_xg[3][SS][BB][HH];           // input-side pre-activations
// h double-buffered, fragment-packed: [buf][b][kpair] = (bf16hi pair, bf16lo pair)
__device__ uint2 g_hp[2][BB][HH / 2];
__device__ __nv_bfloat16 g_xb_hi[BB * SS * II]; // X pre-split to bf16 hi/lo
__device__ __nv_bfloat16 g_xb_lo[BB * SS * II];
__device__ __nv_bfloat16 g_wb_hi[3][HH * II];   // W_f/o/c pre-split
__device__ __nv_bfloat16 g_wb_lo[3][HH * II];

// grid barrier: 8 arrival buckets (16 CTAs each) + release generation
__device__ unsigned g_cnt[8];
__device__ unsigned g_gen;

__device__ __forceinline__ void grid_sync(unsigned gen) {
    __threadfence();
    __syncthreads();
    if (blockIdx.x == 0) {
        if (threadIdx.x == 0) atomicAdd(&g_cnt[0], 1u);
        if (threadIdx.x < 8) {
            while (*(volatile unsigned*)&g_cnt[threadIdx.x] < 16u * gen) __nanosleep(32);
        }
        __syncthreads();
        if (threadIdx.x == 0) atomicExch(&g_gen, gen);
    } else {
        if (threadIdx.x == 0) {
            atomicAdd(&g_cnt[blockIdx.x & 7], 1u);
            while (*(volatile unsigned*)&g_gen < gen) __nanosleep(32);
        }
        __syncthreads();
    }
    __threadfence();
}

__global__ void k_reset() {
    if (threadIdx.x < 8) g_cnt[threadIdx.x] = 0;
    if (threadIdx.x == 0) g_gen = 0;
}

// ---------------------------------------------------------------------------
// HMMA + helpers
// ---------------------------------------------------------------------------
#define MMA(d, a0, a1, a2, a3, b0, b1)                                        \
    asm volatile("mma.sync.aligned.m16n8k16.row.col.f32.bf16.bf16.f32 "       \
        "{%0,%1,%2,%3}, {%4,%5,%6,%7}, {%8,%9}, {%0,%1,%2,%3};"               \
        : "+f"((d)[0]), "+f"((d)[1]), "+f"((d)[2]), "+f"((d)[3])              \
        : "r"(a0), "r"(a1), "r"(a2), "r"(a3), "r"(b0), "r"(b1))

#define LDMATRIX_X2(b0, b1, addr)                                             \
    asm volatile("ldmatrix.sync.aligned.m8n8.x2.shared.b16 {%0,%1}, [%2];"    \
        : "=r"(b0), "=r"(b1) : "r"(addr))

__device__ __forceinline__ void split2(float x0, float x1, uint32_t& hi, uint32_t& lo) {
    __nv_bfloat16 h0 = __float2bfloat16_rn(x0);
    __nv_bfloat16 h1 = __float2bfloat16_rn(x1);
    __nv_bfloat16 l0 = __float2bfloat16_rn(x0 - __bfloat162float(h0));
    __nv_bfloat16 l1 = __float2bfloat16_rn(x1 - __bfloat162float(h1));
    hi = ((uint32_t)__bfloat16_as_ushort(h1) << 16) | (uint32_t)__bfloat16_as_ushort(h0);
    lo = ((uint32_t)__bfloat16_as_ushort(l1) << 16) | (uint32_t)__bfloat16_as_ushort(l0);
}

__device__ __forceinline__ uint32_t smem_u32(const void* p) {
    uint32_t a;
    asm("{ .reg .u64 t; cvta.to.shared.u64 t, %1; cvt.u32.u64 %0, t; }" : "=r"(a) : "l"(p));
    return a;
}

__device__ __forceinline__ float fast_sigmoid(float x) {
    return __fdividef(1.0f, 1.0f + __expf(-x));
}
__device__ __forceinline__ float fast_tanh(float x) {
    float ax = fabsf(x);
    float e  = __expf(ax + ax);
    float r  = 1.0f - __fdividef(2.0f, e + 1.0f);
    return copysignf(r, x);
}

// ---------------------------------------------------------------------------
// K0: convert fp32 -> bf16 hi/lo once. which: 0 = X, 1..3 = W_{f,o,c}
// ---------------------------------------------------------------------------
__global__ __launch_bounds__(256) void k_conv(const float* __restrict__ src,
                                              int which, int n4) {
    __nv_bfloat16* dhi = (which == 0) ? g_xb_hi : g_wb_hi[which - 1];
    __nv_bfloat16* dlo = (which == 0) ? g_xb_lo : g_wb_lo[which - 1];
    int stride = gridDim.x * 256;
    for (int q = blockIdx.x * 256 + threadIdx.x; q < n4; q += stride) {
        float4 v = ((const float4*)src)[q];
        uint32_t h0, l0, h1, l1;
        split2(v.x, v.y, h0, l0);
        split2(v.z, v.w, h1, l1);
        ((uint2*)dhi)[q] = make_uint2(h0, h1);
        ((uint2*)dlo)[q] = make_uint2(l0, l1);
    }
}

// ---------------------------------------------------------------------------
// K1: input-side GEMM via HMMA bf16 3-term split (pre-converted operands).
// M = 32768, N = 3x1024, K = 1024. CTA 128x128, k-step 32, 8 warps (2m x 4n).
// ---------------------------------------------------------------------------
#define IPITCH 40
__global__ __launch_bounds__(256, 2) void k_ingemm(
    const float* __restrict__ bf, const float* __restrict__ bo, const float* __restrict__ bc)
{
    __shared__ __align__(16) uint16_t Ahi[128 * IPITCH], Alo[128 * IPITCH];
    __shared__ __align__(16) uint16_t Bhi[128 * IPITCH], Blo[128 * IPITCH];

    const int bm = blockIdx.x;
    const int bn = blockIdx.y;
    const int g  = bn >> 3;
    const int col0 = (bn & 7) << 7;

    const float* bg = (g == 0) ? bf : (g == 1) ? bo : bc;

    const int tid  = threadIdx.x;
    const int wid  = tid >> 5;
    const int lane = tid & 31;
    const int gq   = lane >> 2;
    const int tg   = lane & 3;
    const int wm   = wid >> 2;
    const int wn   = wid & 3;

    const int lr = tid >> 1;
    const int lq = tid & 1;

    const __nv_bfloat16* Aph = g_xb_hi + (size_t)(bm * 128 + lr) * II;
    const __nv_bfloat16* Apl = g_xb_lo + (size_t)(bm * 128 + lr) * II;
    const __nv_bfloat16* Bph = g_wb_hi[g] + (size_t)(col0 + lr) * II;
    const __nv_bfloat16* Bpl = g_wb_lo[g] + (size_t)(col0 + lr) * II;

    float acc[4][4][4] = {};

    for (int k0 = 0; k0 < II; k0 += 32) {
        __syncthreads();
        #pragma unroll
        for (int j = 0; j < 2; j++) {
            const int kb = lq * 16 + j * 8;
            *(uint4*)&Ahi[lr * IPITCH + kb] = *(const uint4*)(Aph + k0 + kb);
            *(uint4*)&Alo[lr * IPITCH + kb] = *(const uint4*)(Apl + k0 + kb);
            *(uint4*)&Bhi[lr * IPITCH + kb] = *(const uint4*)(Bph + k0 + kb);
            *(uint4*)&Blo[lr * IPITCH + kb] = *(const uint4*)(Bpl + k0 + kb);
        }
        __syncthreads();

        #pragma unroll
        for (int kk = 0; kk < 2; kk++) {
            const int kb = kk * 16 + tg * 2;
            uint32_t ah[4][4], al[4][4];
            #pragma unroll
            for (int mi = 0; mi < 4; mi++) {
                int r0 = wm * 64 + mi * 16 + gq;
                ah[mi][0] = *(uint32_t*)&Ahi[r0 * IPITCH + kb];
                ah[mi][1] = *(uint32_t*)&Ahi[(r0 + 8) * IPITCH + kb];
                ah[mi][2] = *(uint32_t*)&Ahi[r0 * IPITCH + kb + 8];
                ah[mi][3] = *(uint32_t*)&Ahi[(r0 + 8) * IPITCH + kb + 8];
                al[mi][0] = *(uint32_t*)&Alo[r0 * IPITCH + kb];
                al[mi][1] = *(uint32_t*)&Alo[(r0 + 8) * IPITCH + kb];
                al[mi][2] = *(uint32_t*)&Alo[r0 * IPITCH + kb + 8];
                al[mi][3] = *(uint32_t*)&Alo[(r0 + 8) * IPITCH + kb + 8];
            }
            #pragma unroll
            for (int ni = 0; ni < 4; ni++) {
                int n0 = wn * 32 + ni * 8 + gq;
                uint32_t bh0 = *(uint32_t*)&Bhi[n0 * IPITCH + kb];
                uint32_t bh1 = *(uint32_t*)&Bhi[n0 * IPITCH + kb + 8];
                uint32_t bl0 = *(uint32_t*)&Blo[n0 * IPITCH + kb];
                uint32_t bl1 = *(uint32_t*)&Blo[n0 * IPITCH + kb + 8];
                #pragma unroll
                for (int mi = 0; mi < 4; mi++)
                    MMA(acc[mi][ni], ah[mi][0], ah[mi][1], ah[mi][2], ah[mi][3], bh0, bh1);
                #pragma unroll
                for (int mi = 0; mi < 4; mi++)
                    MMA(acc[mi][ni], ah[mi][0], ah[mi][1], ah[mi][2], ah[mi][3], bl0, bl1);
                #pragma unroll
                for (int mi = 0; mi < 4; mi++)
                    MMA(acc[mi][ni], al[mi][0], al[mi][1], al[mi][2], al[mi][3], bh0, bh1);
            }
        }
    }

    #pragma unroll
    for (int mi = 0; mi < 4; mi++) {
        int row0 = bm * 128 + wm * 64 + mi * 16 + gq;
        int b0_ = row0 >> 9,       s0_ = row0 & 511;
        int b1_ = (row0 + 8) >> 9, s1_ = (row0 + 8) & 511;
        #pragma unroll
        for (int ni = 0; ni < 4; ni++) {
            int col = col0 + wn * 32 + ni * 8 + tg * 2;
            float2 bb = {bg[col], bg[col + 1]};
            *(float2*)&g_xg[g][s0_][b0_][col] = make_float2(acc[mi][ni][0] + bb.x, acc[mi][ni][1] + bb.y);
            *(float2*)&g_xg[g][s1_][b1_][col] = make_float2(acc[mi][ni][2] + bb.x, acc[mi][ni][3] + bb.y);
        }
    }
}

// ---------------------------------------------------------------------------
// K2: persistent column-owning scan. 128 CTAs x 256 thr; CTA owns 8 H-cols.
// U (8 cols x 3 gates x 1024 K, bf16 hi/lo) resident in SMEM all 512 steps.
// 8 warps = 4 m-frags (16 batch rows) x 2 K-halves (512 each).
// A-fragments LDG.64 direct from packed h; B via ldmatrix. c in registers.
// One grid_sync per step; h double-buffered.
// ---------------------------------------------------------------------------
#define OFF_RED (3 * 2 * 8 * UPITCH * 2)            // 99072
#define SMEM_SCAN (OFF_RED + 4 * 3 * 4 * 32 * 4)    // 105216

__global__ __launch_bounds__(NTHR_SCAN) void k_scan(
    const float* __restrict__ Uf, const float* __restrict__ Uo, const float* __restrict__ Uc,
    float* __restrict__ out)
{
    extern __shared__ char smem[];
    uint16_t* Usm = (uint16_t*)smem;                 // [gate][term][8 rows][UPITCH]
    float*    red = (float*)(smem + OFF_RED);        // [mi][gate][reg][lane]

    const int cta = blockIdx.x;                      // 0..127
    const int colbase = cta * 8;

    const int tid  = threadIdx.x;
    const int wid  = tid >> 5;
    const int lane = tid & 31;
    const int gq   = lane >> 2;
    const int tg   = lane & 3;
    const int mi   = wid & 3;                        // batch 16-row block
    const int kh   = wid >> 2;                       // K half (0: 0-511, 1: 512-1023)
    const int m0   = mi * 16;
    const int gtid = cta * NTHR_SCAN + tid;

    // ---- load this CTA's U slice (3 gates x 8 rows x 1024) hi/lo into SMEM ----
    const float* Usrc[3] = {Uf, Uo, Uc};
    for (int q = tid; q < 3 * 8 * 256; q += NTHR_SCAN) {   // float4 slots
        int g   = q >> 11;             // /2048
        int r   = (q >> 8) & 7;
        int k   = (q & 255) << 2;
        float4 u = *(const float4*)(Usrc[g] + (size_t)(colbase + r) * HH + k);
        uint32_t h, l;
        uint16_t* uh = Usm + ((g * 2 + 0) * 8 + r) * UPITCH;
        uint16_t* ul = Usm + ((g * 2 + 1) * 8 + r) * UPITCH;
        split2(u.x, u.y, h, l);
        *(uint32_t*)&uh[k]     = h;
        *(uint32_t*)&ul[k]     = l;
        split2(u.z, u.w, h, l);
        *(uint32_t*)&uh[k + 2] = h;
        *(uint32_t*)&ul[k + 2] = l;
    }

    // ---- zero h buffer 0 (graph replays must not inherit state) ----
    ((uint2*)g_hp)[gtid] = make_uint2(0u, 0u);       // exactly 32768 threads, 32768 slots

    // per-thread ldmatrix base addresses (6: gate x hi/lo), incl. K-half offset
    const int l16 = lane & 15;
    uint32_t ubase[6];
    #pragma unroll
    for (int j = 0; j < 6; j++)
        ubase[j] = smem_u32(Usm) + ((j * 8 + (l16 & 7)) * UPITCH) * 2
                 + ((l16 >> 3) * 16) + kh * 1024;

    // c state in registers for this thread's 4 output cells
    float cc0 = 0.0f, cc1 = 0.0f, cc2 = 0.0f, cc3 = 0.0f;
    const int b0_ = m0 + gq;
    const int b1_ = b0_ + 8;
    const int c0  = colbase + tg * 2;

    unsigned gen = 1;
    grid_sync(gen++);

    for (int t = 0; t < SS; t++) {
        const int rb = t & 1, wb = rb ^ 1;

        // ---- phase A: acc[3 gates] += h(K-half) @ U^T, fragments from global ----
        const uint2* hpr0 = &g_hp[rb][b0_][kh * 256 + tg];
        const uint2* hpr1 = &g_hp[rb][b1_][kh * 256 + tg];

        float acc[3][4] = {};
        #pragma unroll 4
        for (int ks = 0; ks < 32; ks++) {
            uint2 v0 = hpr0[ks * 8];
            uint2 v1 = hpr1[ks * 8];
            uint2 v2 = hpr0[ks * 8 + 4];
            uint2 v3 = hpr1[ks * 8 + 4];
            const uint32_t koff = ks * 32;
            #pragma unroll
            for (int g = 0; g < 3; g++) {
                uint32_t bh0, bh1, bl0, bl1;
                LDMATRIX_X2(bh0, bh1, ubase[g * 2 + 0] + koff);
                LDMATRIX_X2(bl0, bl1, ubase[g * 2 + 1] + koff);
                MMA(acc[g], v0.x, v1.x, v2.x, v3.x, bh0, bh1);
                MMA(acc[g], v0.x, v1.x, v2.x, v3.x, bl0, bl1);
                MMA(acc[g], v0.y, v1.y, v2.y, v3.y, bh0, bh1);
            }
        }

        // ---- CTA-local K reduction: kh=1 warps stash, kh=0 warps add ----
        if (kh == 1) {
            #pragma unroll
            for (int g = 0; g < 3; g++)
                #pragma unroll
                for (int r = 0; r < 4; r++)
                    red[((mi * 3 + g) * 4 + r) * 32 + lane] = acc[g][r];
        }
        __syncthreads();

        if (kh == 0) {
            #pragma unroll
            for (int g = 0; g < 3; g++)
                #pragma unroll
                for (int r = 0; r < 4; r++)
                    acc[g][r] += red[((mi * 3 + g) * 4 + r) * 32 + lane];

            // ---- gates + state update (c in registers) ----
            float2 xf0 = *(const float2*)&g_xg[0][t][b0_][c0];
            float2 xf1 = *(const float2*)&g_xg[0][t][b1_][c0];
            float2 xo0 = *(const float2*)&g_xg[1][t][b0_][c0];
            float2 xo1 = *(const float2*)&g_xg[1][t][b1_][c0];
            float2 xc0 = *(const float2*)&g_xg[2][t][b0_][c0];
            float2 xc1 = *(const float2*)&g_xg[2][t][b1_][c0];

            cc0 = fast_sigmoid(xf0.x + acc[0][0]) * cc0 + fast_tanh(xc0.x + acc[2][0]);
            cc1 = fast_sigmoid(xf0.y + acc[0][1]) * cc1 + fast_tanh(xc0.y + acc[2][1]);
            cc2 = fast_sigmoid(xf1.x + acc[0][2]) * cc2 + fast_tanh(xc1.x + acc[2][2]);
            cc3 = fast_sigmoid(xf1.y + acc[0][3]) * cc3 + fast_tanh(xc1.y + acc[2][3]);

            float h0 = fast_sigmoid(xo0.x + acc[1][0]) * cc0;
            float h1 = fast_sigmoid(xo0.y + acc[1][1]) * cc1;
            float h2 = fast_sigmoid(xo1.x + acc[1][2]) * cc2;
            float h3 = fast_sigmoid(xo1.y + acc[1][3]) * cc3;

            // output [b][t][col]
            *(float2*)&out[((size_t)b0_ * SS + t) * HH + c0] = make_float2(h0, h1);
            *(float2*)&out[((size_t)b1_ * SS + t) * HH + c0] = make_float2(h2, h3);

            // packed h for next step's fragments
            uint32_t hh, hl;
            split2(h0, h1, hh, hl);
            g_hp[wb][b0_][(c0 >> 1)] = make_uint2(hh, hl);
            split2(h2, h3, hh, hl);
            g_hp[wb][b1_][(c0 >> 1)] = make_uint2(hh, hl);

            if (t == SS - 1) {   // tail: h[1,B,H], c[1,B,H]
                float* o2 = out + (size_t)BB * SS * HH;
                *(float2*)&o2[b0_ * HH + c0] = make_float2(h0, h1);
                *(float2*)&o2[b1_ * HH + c0] = make_float2(h2, h3);
                float* o3 = o2 + BB * HH;
                *(float2*)&o3[b0_ * HH + c0] = make_float2(cc0, cc1);
                *(float2*)&o3[b1_ * HH + c0] = make_float2(cc2, cc3);
            }
        }

        grid_sync(gen++);
    }
}

extern "C" void kernel_launch(void* const* d_in, const int* in_sizes, int n_in,
                              void* d_out, int out_size) {
    const float* X  = (const float*)d_in[0];
    const float* Wf = (const float*)d_in[1];
    const float* Uf = (const float*)d_in[2];
    const float* bf = (const float*)d_in[3];
    // d_in[4..6] = W_i/U_i/b_i: gate i is computed-but-unused in the reference.
    const float* Wo = (const float*)d_in[7];
    const float* Uo = (const float*)d_in[8];
    const float* bo = (const float*)d_in[9];
    const float* Wc = (const float*)d_in[10];
    const float* Uc = (const float*)d_in[11];
    const float* bc = (const float*)d_in[12];
    float* out = (float*)d_out;

    cudaFuncSetAttribute(k_scan, cudaFuncAttributeMaxDynamicSharedMemorySize, SMEM_SCAN);

    k_reset<<<1, 32>>>();
    k_conv<<<4096, 256>>>(X,  0, (BB * SS * II) / 4);
    k_conv<<<1024, 256>>>(Wf, 1, (HH * II) / 4);
    k_conv<<<1024, 256>>>(Wo, 2, (HH * II) / 4);
    k_conv<<<1024, 256>>>(Wc, 3, (HH * II) / 4);
    k_ingemm<<<dim3(256, 24), 256>>>(bf, bo, bc);
    k_scan<<<NCTA_SCAN, NTHR_SCAN, SMEM_SCAN>>>(Uf, Uo, Uc, out);
}

// round 7
// speedup vs baseline: 1.3991x; 1.3991x over previous
#include <cuda_runtime.h>
#include <cuda_bf16.h>
#include <math.h>
#include <stdint.h>

#define BB 64
#define SS 512
#define II 1024
#define HH 1024

#define KSPLIT 4                 // scan K-splits (chunk = 256)
#define KCHUNK 256
#define NCTA_SCAN 128            // 32 coltiles (32 cols x 3 gates) x 4 ksplits
#define NTHR_SCAN 256
#define SCAN_THREADS (NCTA_SCAN * NTHR_SCAN)

// ---------------------------------------------------------------------------
// Device globals (no allocation allowed anywhere)
// ---------------------------------------------------------------------------
__device__ float g_xg[3][SS][BB][HH];           // input-side pre-activations
__device__ float g_c[BB * HH];
__device__ float g_part[KSPLIT][3][BB][HH];     // recurrent GEMM partials
__device__ __nv_bfloat16 g_hb_hi[BB * HH];      // h split into bf16 hi/lo
__device__ __nv_bfloat16 g_hb_lo[BB * HH];
__device__ __nv_bfloat16 g_xb_hi[BB * SS * II]; // X pre-split to bf16 hi/lo
__device__ __nv_bfloat16 g_xb_lo[BB * SS * II];
__device__ __nv_bfloat16 g_wb_hi[3][HH * II];   // W_f/o/c pre-split
__device__ __nv_bfloat16 g_wb_lo[3][HH * II];

// grid barrier: 8 arrival buckets (16 CTAs each) + release generation
__device__ unsigned g_cnt[8];
__device__ unsigned g_gen;

__device__ __forceinline__ void grid_sync(unsigned gen) {
    __threadfence();
    __syncthreads();
    if (blockIdx.x == 0) {
        if (threadIdx.x == 0) atomicAdd(&g_cnt[0], 1u);
        if (threadIdx.x < 8) {
            while (*(volatile unsigned*)&g_cnt[threadIdx.x] < 16u * gen) { }
        }
        __syncthreads();
        if (threadIdx.x == 0) atomicExch(&g_gen, gen);
    } else {
        if (threadIdx.x == 0) {
            atomicAdd(&g_cnt[blockIdx.x & 7], 1u);
            while (*(volatile unsigned*)&g_gen < gen) { }
        }
        __syncthreads();
    }
    __threadfence();
}

__global__ void k_reset() {
    if (threadIdx.x < 8) g_cnt[threadIdx.x] = 0;
    if (threadIdx.x == 0) g_gen = 0;
}

// ---------------------------------------------------------------------------
// HMMA + ldmatrix + helpers
// ---------------------------------------------------------------------------
#define MMA(d, a0, a1, a2, a3, b0, b1)                                        \
    asm volatile("mma.sync.aligned.m16n8k16.row.col.f32.bf16.bf16.f32 "       \
        "{%0,%1,%2,%3}, {%4,%5,%6,%7}, {%8,%9}, {%0,%1,%2,%3};"               \
        : "+f"((d)[0]), "+f"((d)[1]), "+f"((d)[2]), "+f"((d)[3])              \
        : "r"(a0), "r"(a1), "r"(a2), "r"(a3), "r"(b0), "r"(b1))

#define LDMX4(r, addr)                                                        \
    asm volatile("ldmatrix.sync.aligned.m8n8.x4.shared.b16 {%0,%1,%2,%3}, [%4];" \
        : "=r"((r)[0]), "=r"((r)[1]), "=r"((r)[2]), "=r"((r)[3]) : "r"(addr))

__device__ __forceinline__ void split2(float x0, float x1, uint32_t& hi, uint32_t& lo) {
    __nv_bfloat16 h0 = __float2bfloat16_rn(x0);
    __nv_bfloat16 h1 = __float2bfloat16_rn(x1);
    __nv_bfloat16 l0 = __float2bfloat16_rn(x0 - __bfloat162float(h0));
    __nv_bfloat16 l1 = __float2bfloat16_rn(x1 - __bfloat162float(h1));
    hi = ((uint32_t)__bfloat16_as_ushort(h1) << 16) | (uint32_t)__bfloat16_as_ushort(h0);
    lo = ((uint32_t)__bfloat16_as_ushort(l1) << 16) | (uint32_t)__bfloat16_as_ushort(l0);
}

__device__ __forceinline__ uint32_t smem_u32(const void* p) {
    uint32_t a;
    asm("{ .reg .u64 t; cvta.to.shared.u64 t, %1; cvt.u32.u64 %0, t; }" : "=r"(a) : "l"(p));
    return a;
}

__device__ __forceinline__ float fast_sigmoid(float x) {
    return __fdividef(1.0f, 1.0f + __expf(-x));
}
__device__ __forceinline__ float fast_tanh(float x) {
    float ax = fabsf(x);
    float e  = __expf(ax + ax);
    float r  = 1.0f - __fdividef(2.0f, e + 1.0f);
    return copysignf(r, x);
}

// ---------------------------------------------------------------------------
// K0: convert fp32 -> bf16 hi/lo once. which: 0 = X, 1..3 = W_{f,o,c}
// ---------------------------------------------------------------------------
__global__ __launch_bounds__(256) void k_conv(const float* __restrict__ src,
                                              int which, int n4) {
    __nv_bfloat16* dhi = (which == 0) ? g_xb_hi : g_wb_hi[which - 1];
    __nv_bfloat16* dlo = (which == 0) ? g_xb_lo : g_wb_lo[which - 1];
    int stride = gridDim.x * 256;
    for (int q = blockIdx.x * 256 + threadIdx.x; q < n4; q += stride) {
        float4 v = ((const float4*)src)[q];
        uint32_t h0, l0, h1, l1;
        split2(v.x, v.y, h0, l0);
        split2(v.z, v.w, h1, l1);
        ((uint2*)dhi)[q] = make_uint2(h0, h1);
        ((uint2*)dlo)[q] = make_uint2(l0, l1);
    }
}

// ---------------------------------------------------------------------------
// K1: input-side GEMM via HMMA bf16 3-term split (identical to round 5).
// ---------------------------------------------------------------------------
#define IPITCH 40
__global__ __launch_bounds__(256, 2) void k_ingemm(
    const float* __restrict__ bf, const float* __restrict__ bo, const float* __restrict__ bc)
{
    __shared__ __align__(16) uint16_t Ahi[128 * IPITCH], Alo[128 * IPITCH];
    __shared__ __align__(16) uint16_t Bhi[128 * IPITCH], Blo[128 * IPITCH];

    const int bm = blockIdx.x;
    const int bn = blockIdx.y;
    const int g  = bn >> 3;
    const int col0 = (bn & 7) << 7;

    const float* bg = (g == 0) ? bf : (g == 1) ? bo : bc;

    const int tid  = threadIdx.x;
    const int wid  = tid >> 5;
    const int lane = tid & 31;
    const int gq   = lane >> 2;
    const int tg   = lane & 3;
    const int wm   = wid >> 2;
    const int wn   = wid & 3;

    const int lr = tid >> 1;
    const int lq = tid & 1;

    const __nv_bfloat16* Aph = g_xb_hi + (size_t)(bm * 128 + lr) * II;
    const __nv_bfloat16* Apl = g_xb_lo + (size_t)(bm * 128 + lr) * II;
    const __nv_bfloat16* Bph = g_wb_hi[g] + (size_t)(col0 + lr) * II;
    const __nv_bfloat16* Bpl = g_wb_lo[g] + (size_t)(col0 + lr) * II;

    float acc[4][4][4] = {};

    for (int k0 = 0; k0 < II; k0 += 32) {
        __syncthreads();
        #pragma unroll
        for (int j = 0; j < 2; j++) {
            const int kb = lq * 16 + j * 8;
            *(uint4*)&Ahi[lr * IPITCH + kb] = *(const uint4*)(Aph + k0 + kb);
            *(uint4*)&Alo[lr * IPITCH + kb] = *(const uint4*)(Apl + k0 + kb);
            *(uint4*)&Bhi[lr * IPITCH + kb] = *(const uint4*)(Bph + k0 + kb);
            *(uint4*)&Blo[lr * IPITCH + kb] = *(const uint4*)(Bpl + k0 + kb);
        }
        __syncthreads();

        #pragma unroll
        for (int kk = 0; kk < 2; kk++) {
            const int kb = kk * 16 + tg * 2;
            uint32_t ah[4][4], al[4][4];
            #pragma unroll
            for (int mi = 0; mi < 4; mi++) {
                int r0 = wm * 64 + mi * 16 + gq;
                ah[mi][0] = *(uint32_t*)&Ahi[r0 * IPITCH + kb];
                ah[mi][1] = *(uint32_t*)&Ahi[(r0 + 8) * IPITCH + kb];
                ah[mi][2] = *(uint32_t*)&Ahi[r0 * IPITCH + kb + 8];
                ah[mi][3] = *(uint32_t*)&Ahi[(r0 + 8) * IPITCH + kb + 8];
                al[mi][0] = *(uint32_t*)&Alo[r0 * IPITCH + kb];
                al[mi][1] = *(uint32_t*)&Alo[(r0 + 8) * IPITCH + kb];
                al[mi][2] = *(uint32_t*)&Alo[r0 * IPITCH + kb + 8];
                al[mi][3] = *(uint32_t*)&Alo[(r0 + 8) * IPITCH + kb + 8];
            }
            #pragma unroll
            for (int ni = 0; ni < 4; ni++) {
                int n0 = wn * 32 + ni * 8 + gq;
                uint32_t bh0 = *(uint32_t*)&Bhi[n0 * IPITCH + kb];
                uint32_t bh1 = *(uint32_t*)&Bhi[n0 * IPITCH + kb + 8];
                uint32_t bl0 = *(uint32_t*)&Blo[n0 * IPITCH + kb];
                uint32_t bl1 = *(uint32_t*)&Blo[n0 * IPITCH + kb + 8];
                #pragma unroll
                for (int mi = 0; mi < 4; mi++)
                    MMA(acc[mi][ni], ah[mi][0], ah[mi][1], ah[mi][2], ah[mi][3], bh0, bh1);
                #pragma unroll
                for (int mi = 0; mi < 4; mi++)
                    MMA(acc[mi][ni], ah[mi][0], ah[mi][1], ah[mi][2], ah[mi][3], bl0, bl1);
                #pragma unroll
                for (int mi = 0; mi < 4; mi++)
                    MMA(acc[mi][ni], al[mi][0], al[mi][1], al[mi][2], al[mi][3], bh0, bh1);
            }
        }
    }

    #pragma unroll
    for (int mi = 0; mi < 4; mi++) {
        int row0 = bm * 128 + wm * 64 + mi * 16 + gq;
        int b0_ = row0 >> 9,       s0_ = row0 & 511;
        int b1_ = (row0 + 8) >> 9, s1_ = (row0 + 8) & 511;
        #pragma unroll
        for (int ni = 0; ni < 4; ni++) {
            int col = col0 + wn * 32 + ni * 8 + tg * 2;
            float2 bb = {bg[col], bg[col + 1]};
            *(float2*)&g_xg[g][s0_][b0_][col] = make_float2(acc[mi][ni][0] + bb.x, acc[mi][ni][1] + bb.y);
            *(float2*)&g_xg[g][s1_][b1_][col] = make_float2(acc[mi][ni][2] + bb.x, acc[mi][ni][3] + bb.y);
        }
    }
}

// ---------------------------------------------------------------------------
// K2: persistent HMMA scan. 128 CTAs x 256 thr.
// Per CTA: coltile(32: 32 cols x ALL 3 gates = 96 U-rows) x ksplit(4: K=256).
// U slice resident in SMEM all 512 steps (hi/lo). Per step: stage h,
// ldmatrix+HMMA (8 warps = 4 mi x 2 nj; warp = 16 b x 48 urows x K256),
// write partials, grid_sync, fused phase B, grid_sync.
// SPITCH 264 (132 words == 4 mod 32 -> conflict-free LDSM).
// ---------------------------------------------------------------------------
#define SPITCH 264
#define OFF_U_HI 0
#define OFF_U_LO (OFF_U_HI + 96 * SPITCH * 2)    //  50688
#define OFF_H_HI (OFF_U_LO + 96 * SPITCH * 2)    // 101376
#define OFF_H_LO (OFF_H_HI + 64 * SPITCH * 2)    // 135168
#define SMEM_SCAN (OFF_H_LO + 64 * SPITCH * 2)   // 168960

__global__ __launch_bounds__(NTHR_SCAN) void k_scan(
    const float* __restrict__ Uf, const float* __restrict__ Uo, const float* __restrict__ Uc,
    float* __restrict__ out)
{
    extern __shared__ char smem[];
    uint16_t* Uh = (uint16_t*)(smem + OFF_U_HI);   // [urow 0..95][SPITCH]
    uint16_t* Ul = (uint16_t*)(smem + OFF_U_LO);
    uint16_t* Hh = (uint16_t*)(smem + OFF_H_HI);   // [b 0..63][SPITCH]
    uint16_t* Hl = (uint16_t*)(smem + OFF_H_LO);

    const int cta  = blockIdx.x;          // 0..127
    const int ct   = cta >> 2;            // coltile 0..31 (32 cols)
    const int ks   = cta & 3;             // ksplit (K=256)
    const int kbeg = ks * KCHUNK;
    const int colbase = ct * 32;

    const int tid  = threadIdx.x;
    const int wid  = tid >> 5;
    const int lane = tid & 31;
    const int gq   = lane >> 2;
    const int tg   = lane & 3;
    const int mi   = wid & 3;             // 16-batch-row block
    const int nj   = wid >> 2;            // 48-urow block (0..1)
    const int gtid = cta * NTHR_SCAN + tid;

    // ---- convert U slice (3 gates x 32 cols x 256 k) to bf16 hi/lo SMEM ----
    const float* Usrc[3] = {Uf, Uo, Uc};
    for (int q = tid; q < 96 * 64; q += NTHR_SCAN) {   // float4 slots
        int urow = q >> 6;                // 0..95: gate*32 + r
        int g    = urow >> 5;
        int r    = urow & 31;
        int k    = (q & 63) << 2;
        float4 u = *(const float4*)(Usrc[g] + (size_t)(colbase + r) * HH + kbeg + k);
        uint32_t h, l;
        split2(u.x, u.y, h, l);
        *(uint32_t*)&Uh[urow * SPITCH + k]     = h;
        *(uint32_t*)&Ul[urow * SPITCH + k]     = l;
        split2(u.z, u.w, h, l);
        *(uint32_t*)&Uh[urow * SPITCH + k + 2] = h;
        *(uint32_t*)&Ul[urow * SPITCH + k + 2] = l;
    }

    // ---- zero state ----
    for (int i = gtid; i < BB * HH; i += SCAN_THREADS) {
        g_c[i] = 0.0f;
        g_hb_hi[i] = __ushort_as_bfloat16(0);
        g_hb_lo[i] = __ushort_as_bfloat16(0);
    }

    // ---- per-thread ldmatrix base addresses ----
    const uint32_t sb = smem_u32(smem);
    // A (h tile): rows mi*16 + (l&7) + ((l>>3)&1)*8, kcol ((l>>4)&1)*8
    const int arow = mi * 16 + (lane & 7) + ((lane >> 3) & 1) * 8;
    const int akc  = ((lane >> 4) & 1) * 8;
    const uint32_t aH = sb + OFF_H_HI + (arow * SPITCH + akc) * 2;
    const uint32_t aL = sb + OFF_H_LO + (arow * SPITCH + akc) * 2;
    // B (U tile), x4 covers ni pair + both k-halves:
    // row = nj*48 + j*16 + (l&7) + ((l>>4)&1)*8, kcol ((l>>3)&1)*8
    const int brow = (lane & 7) + ((lane >> 4) & 1) * 8;
    const int bkc  = ((lane >> 3) & 1) * 8;
    uint32_t bH[3], bL[3];
    #pragma unroll
    for (int j = 0; j < 3; j++) {
        int r = nj * 48 + j * 16 + brow;
        bH[j] = sb + OFF_U_HI + (r * SPITCH + bkc) * 2;
        bL[j] = sb + OFF_U_LO + (r * SPITCH + bkc) * 2;
    }

    const int b0_ = mi * 16 + gq;
    const int b1_ = b0_ + 8;

    unsigned gen = 1;
    grid_sync(gen++);

    for (int t = 0; t < SS; t++) {
        // ---- stage h tiles (64 x 256 bf16, hi+lo) into SMEM ----
        #pragma unroll
        for (int i = 0; i < 8; i++) {
            int q = tid + i * NTHR_SCAN;  // 0..2047 uint4 slots per term
            int row = q >> 5;             // 0..63 (batch)
            int pos = q & 31;             // 16B chunk within 512B row
            const char* sh = (const char*)g_hb_hi + (size_t)row * 2048 + kbeg * 2 + pos * 16;
            const char* sl = (const char*)g_hb_lo + (size_t)row * 2048 + kbeg * 2 + pos * 16;
            *(uint4*)((char*)Hh + row * (SPITCH * 2) + pos * 16) = *(const uint4*)sh;
            *(uint4*)((char*)Hl + row * (SPITCH * 2) + pos * 16) = *(const uint4*)sl;
        }
        __syncthreads();

        // ---- HMMA: D[16 b][48 urows] per warp, K=256, 3-term split ----
        float acc[6][4] = {};
        #pragma unroll 2
        for (int kk = 0; kk < 16; kk++) {
            const uint32_t ko = kk * 32;
            uint32_t a_h[4], a_l[4];
            LDMX4(a_h, aH + ko);
            LDMX4(a_l, aL + ko);
            #pragma unroll
            for (int j = 0; j < 3; j++) {
                uint32_t bh[4], bl[4];
                LDMX4(bh, bH[j] + ko);
                LDMX4(bl, bL[j] + ko);
                MMA(acc[j*2],   a_h[0], a_h[1], a_h[2], a_h[3], bh[0], bh[1]);
                MMA(acc[j*2],   a_h[0], a_h[1], a_h[2], a_h[3], bl[0], bl[1]);
                MMA(acc[j*2],   a_l[0], a_l[1], a_l[2], a_l[3], bh[0], bh[1]);
                MMA(acc[j*2+1], a_h[0], a_h[1], a_h[2], a_h[3], bh[2], bh[3]);
                MMA(acc[j*2+1], a_h[0], a_h[1], a_h[2], a_h[3], bl[2], bl[3]);
                MMA(acc[j*2+1], a_l[0], a_l[1], a_l[2], a_l[3], bh[2], bh[3]);
            }
        }

        // ---- write partials: urow -> (gate, col) ----
        #pragma unroll
        for (int idx = 0; idx < 6; idx++) {
            int n    = nj * 48 + idx * 8 + tg * 2;
            int g    = n >> 5;
            int col  = colbase + (n & 31);
            *(float2*)&g_part[ks][g][b0_][col] = make_float2(acc[idx][0], acc[idx][1]);
            *(float2*)&g_part[ks][g][b1_][col] = make_float2(acc[idx][2], acc[idx][3]);
        }
        grid_sync(gen++);

        // ---- phase B: float4 per thread; 16384 threads active ----
        if (gtid < 16384) {
            int b_  = gtid >> 8;
            int col = (gtid & 255) << 2;
            float4 pf = *(const float4*)&g_xg[0][t][b_][col];
            float4 po = *(const float4*)&g_xg[1][t][b_][col];
            float4 pc = *(const float4*)&g_xg[2][t][b_][col];
            #pragma unroll
            for (int k = 0; k < KSPLIT; k++) {
                float4 v;
                v = *(const float4*)&g_part[k][0][b_][col];
                pf.x += v.x; pf.y += v.y; pf.z += v.z; pf.w += v.w;
                v = *(const float4*)&g_part[k][1][b_][col];
                po.x += v.x; po.y += v.y; po.z += v.z; po.w += v.w;
                v = *(const float4*)&g_part[k][2][b_][col];
                pc.x += v.x; pc.y += v.y; pc.z += v.z; pc.w += v.w;
            }
            float4 cold = *(const float4*)&g_c[gtid << 2];
            float4 cn, hn;
            cn.x = fast_sigmoid(pf.x) * cold.x + fast_tanh(pc.x);
            cn.y = fast_sigmoid(pf.y) * cold.y + fast_tanh(pc.y);
            cn.z = fast_sigmoid(pf.z) * cold.z + fast_tanh(pc.z);
            cn.w = fast_sigmoid(pf.w) * cold.w + fast_tanh(pc.w);
            hn.x = fast_sigmoid(po.x) * cn.x;
            hn.y = fast_sigmoid(po.y) * cn.y;
            hn.z = fast_sigmoid(po.z) * cn.z;
            hn.w = fast_sigmoid(po.w) * cn.w;
            *(float4*)&g_c[gtid << 2] = cn;

            uint32_t h01, l01, h23, l23;
            split2(hn.x, hn.y, h01, l01);
            split2(hn.z, hn.w, h23, l23);
            *(uint2*)&g_hb_hi[gtid << 2] = make_uint2(h01, h23);
            *(uint2*)&g_hb_lo[gtid << 2] = make_uint2(l01, l23);

            *(float4*)&out[((size_t)b_ * SS + t) * HH + col] = hn;
            if (t == SS - 1) {
                *(float4*)&out[(size_t)BB * SS * HH + (gtid << 2)] = hn;
                *(float4*)&out[(size_t)BB * SS * HH + BB * HH + (gtid << 2)] = cn;
            }
        }
        grid_sync(gen++);
    }
}

extern "C" void kernel_launch(void* const* d_in, const int* in_sizes, int n_in,
                              void* d_out, int out_size) {
    const float* X  = (const float*)d_in[0];
    const float* Wf = (const float*)d_in[1];
    const float* Uf = (const float*)d_in[2];
    const float* bf = (const float*)d_in[3];
    // d_in[4..6] = W_i/U_i/b_i: gate i is computed-but-unused in the reference.
    const float* Wo = (const float*)d_in[7];
    const float* Uo = (const float*)d_in[8];
    const float* bo = (const float*)d_in[9];
    const float* Wc = (const float*)d_in[10];
    const float* Uc = (const float*)d_in[11];
    const float* bc = (const float*)d_in[12];
    float* out = (float*)d_out;

    cudaFuncSetAttribute(k_scan, cudaFuncAttributeMaxDynamicSharedMemorySize, SMEM_SCAN);

    k_reset<<<1, 32>>>();
    k_conv<<<4096, 256>>>(X,  0, (BB * SS * II) / 4);
    k_conv<<<1024, 256>>>(Wf, 1, (HH * II) / 4);
    k_conv<<<1024, 256>>>(Wo, 2, (HH * II) / 4);
    k_conv<<<1024, 256>>>(Wc, 3, (HH * II) / 4);
    k_ingemm<<<dim3(256, 24), 256>>>(bf, bo, bc);
    k_scan<<<NCTA_SCAN, NTHR_SCAN, SMEM_SCAN>>>(Uf, Uo, Uc, out);
}

// round 8
// speedup vs baseline: 1.6102x; 1.1509x over previous
#include <cuda_runtime.h>
#include <cuda_bf16.h>
#include <math.h>
#include <stdint.h>

#define BB 64
#define SS 512
#define II 1024
#define HH 1024

#define KSPLIT 4                 // scan K-splits (chunk = 256)
#define KCHUNK 256
#define NCTA_SCAN 128            // 32 coltiles (32 cols x 3 gates) x 4 ksplits
#define NTHR_SCAN 256
#define SCAN_THREADS (NCTA_SCAN * NTHR_SCAN)

// ---------------------------------------------------------------------------
// Device globals (no allocation allowed anywhere)
// ---------------------------------------------------------------------------
__device__ float g_xg[3][SS][BB][HH];           // input-side pre-activations
__device__ float g_part[KSPLIT][3][BB][HH];     // recurrent GEMM partials
__device__ __nv_bfloat16 g_hb_hi[BB * HH];      // h split into bf16 hi/lo
__device__ __nv_bfloat16 g_hb_lo[BB * HH];
__device__ __nv_bfloat16 g_xb_hi[BB * SS * II]; // X pre-split to bf16 hi/lo
__device__ __nv_bfloat16 g_xb_lo[BB * SS * II];
__device__ __nv_bfloat16 g_wb_hi[3][HH * II];   // W_f/o/c pre-split
__device__ __nv_bfloat16 g_wb_lo[3][HH * II];

// grid barrier: 8 arrival buckets (16 CTAs each) + release generation
__device__ unsigned g_cnt[8];
__device__ unsigned g_gen;

__device__ __forceinline__ unsigned ld_acq(const unsigned* p) {
    unsigned v;
    asm volatile("ld.acquire.gpu.global.u32 %0, [%1];" : "=r"(v) : "l"(p));
    return v;
}
__device__ __forceinline__ void red_rel_add(unsigned* p, unsigned v) {
    asm volatile("red.release.gpu.global.add.u32 [%0], %1;" :: "l"(p), "r"(v) : "memory");
}
__device__ __forceinline__ void st_rel(unsigned* p, unsigned v) {
    asm volatile("st.release.gpu.global.u32 [%0], %1;" :: "l"(p), "r"(v) : "memory");
}

__device__ __forceinline__ void grid_sync(unsigned gen) {
    __syncthreads();
    if (blockIdx.x == 0) {
        if (threadIdx.x == 0) red_rel_add(&g_cnt[0], 1u);
        if (threadIdx.x < 8) {
            while (ld_acq(&g_cnt[threadIdx.x]) < 16u * gen) { }
        }
        __syncthreads();
        if (threadIdx.x == 0) st_rel(&g_gen, gen);
    } else {
        if (threadIdx.x == 0) {
            red_rel_add(&g_cnt[blockIdx.x & 7], 1u);
            while (ld_acq(&g_gen) < gen) { }
        }
        __syncthreads();
    }
}

__global__ void k_reset() {
    if (threadIdx.x < 8) g_cnt[threadIdx.x] = 0;
    if (threadIdx.x == 0) g_gen = 0;
}

// ---------------------------------------------------------------------------
// HMMA + ldmatrix + helpers
// ---------------------------------------------------------------------------
#define MMA(d, a0, a1, a2, a3, b0, b1)                                        \
    asm volatile("mma.sync.aligned.m16n8k16.row.col.f32.bf16.bf16.f32 "       \
        "{%0,%1,%2,%3}, {%4,%5,%6,%7}, {%8,%9}, {%0,%1,%2,%3};"               \
        : "+f"((d)[0]), "+f"((d)[1]), "+f"((d)[2]), "+f"((d)[3])              \
        : "r"(a0), "r"(a1), "r"(a2), "r"(a3), "r"(b0), "r"(b1))

#define LDMX4(r, addr)                                                        \
    asm volatile("ldmatrix.sync.aligned.m8n8.x4.shared.b16 {%0,%1,%2,%3}, [%4];" \
        : "=r"((r)[0]), "=r"((r)[1]), "=r"((r)[2]), "=r"((r)[3]) : "r"(addr))

__device__ __forceinline__ void split2(float x0, float x1, uint32_t& hi, uint32_t& lo) {
    __nv_bfloat16 h0 = __float2bfloat16_rn(x0);
    __nv_bfloat16 h1 = __float2bfloat16_rn(x1);
    __nv_bfloat16 l0 = __float2bfloat16_rn(x0 - __bfloat162float(h0));
    __nv_bfloat16 l1 = __float2bfloat16_rn(x1 - __bfloat162float(h1));
    hi = ((uint32_t)__bfloat16_as_ushort(h1) << 16) | (uint32_t)__bfloat16_as_ushort(h0);
    lo = ((uint32_t)__bfloat16_as_ushort(l1) << 16) | (uint32_t)__bfloat16_as_ushort(l0);
}

__device__ __forceinline__ uint32_t smem_u32(const void* p) {
    uint32_t a;
    asm("{ .reg .u64 t; cvta.to.shared.u64 t, %1; cvt.u32.u64 %0, t; }" : "=r"(a) : "l"(p));
    return a;
}

__device__ __forceinline__ float fast_sigmoid(float x) {
    return __fdividef(1.0f, 1.0f + __expf(-x));
}
__device__ __forceinline__ float fast_tanh(float x) {
    float ax = fabsf(x);
    float e  = __expf(ax + ax);
    float r  = 1.0f - __fdividef(2.0f, e + 1.0f);
    return copysignf(r, x);
}

// ---------------------------------------------------------------------------
// K0: convert fp32 -> bf16 hi/lo once. which: 0 = X, 1..3 = W_{f,o,c}
// ---------------------------------------------------------------------------
__global__ __launch_bounds__(256) void k_conv(const float* __restrict__ src,
                                              int which, int n4) {
    __nv_bfloat16* dhi = (which == 0) ? g_xb_hi : g_wb_hi[which - 1];
    __nv_bfloat16* dlo = (which == 0) ? g_xb_lo : g_wb_lo[which - 1];
    int stride = gridDim.x * 256;
    for (int q = blockIdx.x * 256 + threadIdx.x; q < n4; q += stride) {
        float4 v = ((const float4*)src)[q];
        uint32_t h0, l0, h1, l1;
        split2(v.x, v.y, h0, l0);
        split2(v.z, v.w, h1, l1);
        ((uint2*)dhi)[q] = make_uint2(h0, h1);
        ((uint2*)dlo)[q] = make_uint2(l0, l1);
    }
}

// ---------------------------------------------------------------------------
// K1: input-side GEMM via HMMA bf16 3-term split, ldmatrix fragments.
// M = 32768, N = 3x1024, K = 1024. CTA 128x128, k-step 32, 8 warps (2m x 4n).
// ---------------------------------------------------------------------------
#define IPITCH 40
__global__ __launch_bounds__(256, 2) void k_ingemm(
    const float* __restrict__ bf, const float* __restrict__ bo, const float* __restrict__ bc)
{
    __shared__ __align__(16) uint16_t Ahi[128 * IPITCH], Alo[128 * IPITCH];
    __shared__ __align__(16) uint16_t Bhi[128 * IPITCH], Blo[128 * IPITCH];

    const int bm = blockIdx.x;
    const int bn = blockIdx.y;
    const int g  = bn >> 3;
    const int col0 = (bn & 7) << 7;

    const float* bg = (g == 0) ? bf : (g == 1) ? bo : bc;

    const int tid  = threadIdx.x;
    const int wid  = tid >> 5;
    const int lane = tid & 31;
    const int gq   = lane >> 2;
    const int tg   = lane & 3;
    const int wm   = wid >> 2;
    const int wn   = wid & 3;

    const int lr = tid >> 1;
    const int lq = tid & 1;

    const __nv_bfloat16* Aph = g_xb_hi + (size_t)(bm * 128 + lr) * II;
    const __nv_bfloat16* Apl = g_xb_lo + (size_t)(bm * 128 + lr) * II;
    const __nv_bfloat16* Bph = g_wb_hi[g] + (size_t)(col0 + lr) * II;
    const __nv_bfloat16* Bpl = g_wb_lo[g] + (size_t)(col0 + lr) * II;

    // ldmatrix base addresses (constant across k0 — tile refilled in place)
    const int arow = wm * 64 + (lane & 7) + ((lane >> 3) & 1) * 8;  // + mi*16
    const int akc  = ((lane >> 4) & 1) * 8;
    const int brow = wn * 32 + (lane & 7) + ((lane >> 4) & 1) * 8;  // + p*16
    const int bkc  = ((lane >> 3) & 1) * 8;
    uint32_t aHb[4], aLb[4], bHb[2], bLb[2];
    #pragma unroll
    for (int mi = 0; mi < 4; mi++) {
        aHb[mi] = smem_u32(Ahi) + (((arow + mi * 16) * IPITCH) + akc) * 2;
        aLb[mi] = smem_u32(Alo) + (((arow + mi * 16) * IPITCH) + akc) * 2;
    }
    #pragma unroll
    for (int p = 0; p < 2; p++) {
        bHb[p] = smem_u32(Bhi) + (((brow + p * 16) * IPITCH) + bkc) * 2;
        bLb[p] = smem_u32(Blo) + (((brow + p * 16) * IPITCH) + bkc) * 2;
    }

    float acc[4][4][4] = {};

    for (int k0 = 0; k0 < II; k0 += 32) {
        __syncthreads();
        #pragma unroll
        for (int j = 0; j < 2; j++) {
            const int kb = lq * 16 + j * 8;
            *(uint4*)&Ahi[lr * IPITCH + kb] = *(const uint4*)(Aph + k0 + kb);
            *(uint4*)&Alo[lr * IPITCH + kb] = *(const uint4*)(Apl + k0 + kb);
            *(uint4*)&Bhi[lr * IPITCH + kb] = *(const uint4*)(Bph + k0 + kb);
            *(uint4*)&Blo[lr * IPITCH + kb] = *(const uint4*)(Bpl + k0 + kb);
        }
        __syncthreads();

        #pragma unroll
        for (int kk = 0; kk < 2; kk++) {
            const uint32_t ko = kk * 32;
            uint32_t ah[4][4], al[4][4];
            #pragma unroll
            for (int mi = 0; mi < 4; mi++) {
                LDMX4(ah[mi], aHb[mi] + ko);
                LDMX4(al[mi], aLb[mi] + ko);
            }
            #pragma unroll
            for (int p = 0; p < 2; p++) {
                uint32_t bh[4], bl[4];
                LDMX4(bh, bHb[p] + ko);
                LDMX4(bl, bLb[p] + ko);
                #pragma unroll
                for (int q = 0; q < 2; q++) {
                    const int ni = p * 2 + q;
                    #pragma unroll
                    for (int mi = 0; mi < 4; mi++)
                        MMA(acc[mi][ni], ah[mi][0], ah[mi][1], ah[mi][2], ah[mi][3], bh[2*q], bh[2*q+1]);
                    #pragma unroll
                    for (int mi = 0; mi < 4; mi++)
                        MMA(acc[mi][ni], ah[mi][0], ah[mi][1], ah[mi][2], ah[mi][3], bl[2*q], bl[2*q+1]);
                    #pragma unroll
                    for (int mi = 0; mi < 4; mi++)
                        MMA(acc[mi][ni], al[mi][0], al[mi][1], al[mi][2], al[mi][3], bh[2*q], bh[2*q+1]);
                }
            }
        }
    }

    #pragma unroll
    for (int mi = 0; mi < 4; mi++) {
        int row0 = bm * 128 + wm * 64 + mi * 16 + gq;
        int b0_ = row0 >> 9,       s0_ = row0 & 511;
        int b1_ = (row0 + 8) >> 9, s1_ = (row0 + 8) & 511;
        #pragma unroll
        for (int ni = 0; ni < 4; ni++) {
            int col = col0 + wn * 32 + ni * 8 + tg * 2;
            float2 bb = {bg[col], bg[col + 1]};
            *(float2*)&g_xg[g][s0_][b0_][col] = make_float2(acc[mi][ni][0] + bb.x, acc[mi][ni][1] + bb.y);
            *(float2*)&g_xg[g][s1_][b1_][col] = make_float2(acc[mi][ni][2] + bb.x, acc[mi][ni][3] + bb.y);
        }
    }
}

// ---------------------------------------------------------------------------
// K2: persistent HMMA scan. 128 CTAs x 256 thr.
// Per CTA: coltile(32: 32 cols x 3 gates = 96 U-rows) x ksplit(4: K=256).
// Changes vs round 7: acq/rel barrier, xg prefetch across barrier 1,
// c in registers, phase B on all 32768 threads (float2 each).
// ---------------------------------------------------------------------------
#define SPITCH 264
#define OFF_U_HI 0
#define OFF_U_LO (OFF_U_HI + 96 * SPITCH * 2)    //  50688
#define OFF_H_HI (OFF_U_LO + 96 * SPITCH * 2)    // 101376
#define OFF_H_LO (OFF_H_HI + 64 * SPITCH * 2)    // 135168
#define SMEM_SCAN (OFF_H_LO + 64 * SPITCH * 2)   // 168960

__global__ __launch_bounds__(NTHR_SCAN) void k_scan(
    const float* __restrict__ Uf, const float* __restrict__ Uo, const float* __restrict__ Uc,
    float* __restrict__ out)
{
    extern __shared__ char smem[];
    uint16_t* Uh = (uint16_t*)(smem + OFF_U_HI);   // [urow 0..95][SPITCH]
    uint16_t* Ul = (uint16_t*)(smem + OFF_U_LO);
    uint16_t* Hh = (uint16_t*)(smem + OFF_H_HI);   // [b 0..63][SPITCH]
    uint16_t* Hl = (uint16_t*)(smem + OFF_H_LO);

    const int cta  = blockIdx.x;          // 0..127
    const int ct   = cta >> 2;            // coltile 0..31 (32 cols)
    const int ks   = cta & 3;             // ksplit (K=256)
    const int kbeg = ks * KCHUNK;
    const int colbase = ct * 32;

    const int tid  = threadIdx.x;
    const int wid  = tid >> 5;
    const int lane = tid & 31;
    const int gq   = lane >> 2;
    const int tg   = lane & 3;
    const int mi   = wid & 3;             // 16-batch-row block
    const int nj   = wid >> 2;            // 48-urow block (0..1)
    const int gtid = cta * NTHR_SCAN + tid;

    // ---- convert U slice (3 gates x 32 cols x 256 k) to bf16 hi/lo SMEM ----
    const float* Usrc[3] = {Uf, Uo, Uc};
    for (int q = tid; q < 96 * 64; q += NTHR_SCAN) {   // float4 slots
        int urow = q >> 6;
        int g    = urow >> 5;
        int r    = urow & 31;
        int k    = (q & 63) << 2;
        float4 u = *(const float4*)(Usrc[g] + (size_t)(colbase + r) * HH + kbeg + k);
        uint32_t h, l;
        split2(u.x, u.y, h, l);
        *(uint32_t*)&Uh[urow * SPITCH + k]     = h;
        *(uint32_t*)&Ul[urow * SPITCH + k]     = l;
        split2(u.z, u.w, h, l);
        *(uint32_t*)&Uh[urow * SPITCH + k + 2] = h;
        *(uint32_t*)&Ul[urow * SPITCH + k + 2] = l;
    }

    // ---- zero h (graph replays must not inherit state) ----
    for (int i = gtid; i < BB * HH; i += SCAN_THREADS) {
        g_hb_hi[i] = __ushort_as_bfloat16(0);
        g_hb_lo[i] = __ushort_as_bfloat16(0);
    }

    // ---- per-thread ldmatrix base addresses ----
    const uint32_t sb = smem_u32(smem);
    const int arow = mi * 16 + (lane & 7) + ((lane >> 3) & 1) * 8;
    const int akc  = ((lane >> 4) & 1) * 8;
    const uint32_t aH = sb + OFF_H_HI + (arow * SPITCH + akc) * 2;
    const uint32_t aL = sb + OFF_H_LO + (arow * SPITCH + akc) * 2;
    const int brow = (lane & 7) + ((lane >> 4) & 1) * 8;
    const int bkc  = ((lane >> 3) & 1) * 8;
    uint32_t bH[3], bL[3];
    #pragma unroll
    for (int j = 0; j < 3; j++) {
        int r = nj * 48 + j * 16 + brow;
        bH[j] = sb + OFF_U_HI + (r * SPITCH + bkc) * 2;
        bL[j] = sb + OFF_U_LO + (r * SPITCH + bkc) * 2;
    }

    const int b0_ = mi * 16 + gq;
    const int b1_ = b0_ + 8;

    // phase B fixed mapping: this thread owns (pb_b, pb_col..pb_col+1); c in regs
    const int pb_b   = gtid >> 9;
    const int pb_col = (gtid & 511) << 1;
    float cc0 = 0.0f, cc1 = 0.0f;

    unsigned gen = 1;
    grid_sync(gen++);

    for (int t = 0; t < SS; t++) {
        // ---- stage h tiles (64 x 256 bf16, hi+lo) into SMEM ----
        #pragma unroll
        for (int i = 0; i < 8; i++) {
            int q = tid + i * NTHR_SCAN;
            int row = q >> 5;
            int pos = q & 31;
            const char* sh = (const char*)g_hb_hi + (size_t)row * 2048 + kbeg * 2 + pos * 16;
            const char* sl = (const char*)g_hb_lo + (size_t)row * 2048 + kbeg * 2 + pos * 16;
            *(uint4*)((char*)Hh + row * (SPITCH * 2) + pos * 16) = *(const uint4*)sh;
            *(uint4*)((char*)Hl + row * (SPITCH * 2) + pos * 16) = *(const uint4*)sl;
        }
        __syncthreads();

        // ---- HMMA: D[16 b][48 urows] per warp, K=256, 3-term split ----
        float acc[6][4] = {};
        #pragma unroll 2
        for (int kk = 0; kk < 16; kk++) {
            const uint32_t ko = kk * 32;
            uint32_t a_h[4], a_l[4];
            LDMX4(a_h, aH + ko);
            LDMX4(a_l, aL + ko);
            #pragma unroll
            for (int j = 0; j < 3; j++) {
                uint32_t bh[4], bl[4];
                LDMX4(bh, bH[j] + ko);
                LDMX4(bl, bL[j] + ko);
                MMA(acc[j*2],   a_h[0], a_h[1], a_h[2], a_h[3], bh[0], bh[1]);
                MMA(acc[j*2],   a_h[0], a_h[1], a_h[2], a_h[3], bl[0], bl[1]);
                MMA(acc[j*2],   a_l[0], a_l[1], a_l[2], a_l[3], bh[0], bh[1]);
                MMA(acc[j*2+1], a_h[0], a_h[1], a_h[2], a_h[3], bh[2], bh[3]);
                MMA(acc[j*2+1], a_h[0], a_h[1], a_h[2], a_h[3], bl[2], bl[3]);
                MMA(acc[j*2+1], a_l[0], a_l[1], a_l[2], a_l[3], bh[2], bh[3]);
            }
        }

        // ---- write partials: urow -> (gate, col) ----
        #pragma unroll
        for (int idx = 0; idx < 6; idx++) {
            int n    = nj * 48 + idx * 8 + tg * 2;
            int g    = n >> 5;
            int col  = colbase + (n & 31);
            *(float2*)&g_part[ks][g][b0_][col] = make_float2(acc[idx][0], acc[idx][1]);
            *(float2*)&g_part[ks][g][b1_][col] = make_float2(acc[idx][2], acc[idx][3]);
        }

        // ---- prefetch phase-B gate pre-activations (complete during barrier)
        float2 xf = *(const float2*)&g_xg[0][t][pb_b][pb_col];
        float2 xo = *(const float2*)&g_xg[1][t][pb_b][pb_col];
        float2 xc = *(const float2*)&g_xg[2][t][pb_b][pb_col];

        grid_sync(gen++);

        // ---- phase B: all 32768 threads, float2 each, c in registers ----
        {
            float pf0 = xf.x, pf1 = xf.y;
            float po0 = xo.x, po1 = xo.y;
            float pc0 = xc.x, pc1 = xc.y;
            #pragma unroll
            for (int k = 0; k < KSPLIT; k++) {
                float2 v;
                v = *(const float2*)&g_part[k][0][pb_b][pb_col];
                pf0 += v.x; pf1 += v.y;
                v = *(const float2*)&g_part[k][1][pb_b][pb_col];
                po0 += v.x; po1 += v.y;
                v = *(const float2*)&g_part[k][2][pb_b][pb_col];
                pc0 += v.x; pc1 += v.y;
            }
            cc0 = fast_sigmoid(pf0) * cc0 + fast_tanh(pc0);
            cc1 = fast_sigmoid(pf1) * cc1 + fast_tanh(pc1);
            float h0 = fast_sigmoid(po0) * cc0;
            float h1 = fast_sigmoid(po1) * cc1;

            uint32_t hh, hl;
            split2(h0, h1, hh, hl);
            *(uint32_t*)&g_hb_hi[pb_b * HH + pb_col] = hh;
            *(uint32_t*)&g_hb_lo[pb_b * HH + pb_col] = hl;

            *(float2*)&out[((size_t)pb_b * SS + t) * HH + pb_col] = make_float2(h0, h1);
            if (t == SS - 1) {
                float* o2 = out + (size_t)BB * SS * HH;
                *(float2*)&o2[pb_b * HH + pb_col] = make_float2(h0, h1);
                float* o3 = o2 + BB * HH;
                *(float2*)&o3[pb_b * HH + pb_col] = make_float2(cc0, cc1);
            }
        }
        grid_sync(gen++);
    }
}

extern "C" void kernel_launch(void* const* d_in, const int* in_sizes, int n_in,
                              void* d_out, int out_size) {
    const float* X  = (const float*)d_in[0];
    const float* Wf = (const float*)d_in[1];
    const float* Uf = (const float*)d_in[2];
    const float* bf = (const float*)d_in[3];
    // d_in[4..6] = W_i/U_i/b_i: gate i is computed-but-unused in the reference.
    const float* Wo = (const float*)d_in[7];
    const float* Uo = (const float*)d_in[8];
    const float* bo = (const float*)d_in[9];
    const float* Wc = (const float*)d_in[10];
    const float* Uc = (const float*)d_in[11];
    const float* bc = (const float*)d_in[12];
    float* out = (float*)d_out;

    cudaFuncSetAttribute(k_scan, cudaFuncAttributeMaxDynamicSharedMemorySize, SMEM_SCAN);

    k_reset<<<1, 32>>>();
    k_conv<<<4096, 256>>>(X,  0, (BB * SS * II) / 4);
    k_conv<<<1024, 256>>>(Wf, 1, (HH * II) / 4);
    k_conv<<<1024, 256>>>(Wo, 2, (HH * II) / 4);
    k_conv<<<1024, 256>>>(Wc, 3, (HH * II) / 4);
    k_ingemm<<<dim3(256, 24), 256>>>(bf, bo, bc);
    k_scan<<<NCTA_SCAN, NTHR_SCAN, SMEM_SCAN>>>(Uf, Uo, Uc, out);
}

// round 9
// speedup vs baseline: 1.8595x; 1.1548x over previous
#include <cuda_runtime.h>
#include <cuda_bf16.h>
#include <math.h>
#include <stdint.h>

#define BB 64
#define SS 512
#define II 1024
#define HH 1024

#define KSPLIT 4                 // scan K-splits (chunk = 256)
#define KCHUNK 256
#define NCTA_SCAN 128            // 32 coltiles (32 cols x 3 gates) x 4 ksplits
#define NTHR_SCAN 256
#define SCAN_THREADS (NCTA_SCAN * NTHR_SCAN)

// ---------------------------------------------------------------------------
// Device globals (no allocation allowed anywhere)
// ---------------------------------------------------------------------------
__device__ float g_xg[3][SS][BB][HH];           // input-side pre-activations
__device__ float g_part[KSPLIT][3][BB][HH];     // recurrent GEMM partials
__device__ __nv_bfloat16 g_hb_hi[BB * HH];      // h split into bf16 hi/lo
__device__ __nv_bfloat16 g_hb_lo[BB * HH];
__device__ __nv_bfloat16 g_xb_hi[BB * SS * II]; // X pre-split to bf16 hi/lo
__device__ __nv_bfloat16 g_xb_lo[BB * SS * II];
__device__ __nv_bfloat16 g_wb_hi[3][HH * II];   // W_f/o/c pre-split
__device__ __nv_bfloat16 g_wb_lo[3][HH * II];

// grid barrier: 16 arrival buckets (8 CTAs each); every CTA polls all buckets
__device__ unsigned g_cnt[16];

__device__ __forceinline__ unsigned ld_acq(const unsigned* p) {
    unsigned v;
    asm volatile("ld.acquire.gpu.global.u32 %0, [%1];" : "=r"(v) : "l"(p));
    return v;
}
__device__ __forceinline__ void red_rel_add(unsigned* p, unsigned v) {
    asm volatile("red.release.gpu.global.add.u32 [%0], %1;" :: "l"(p), "r"(v) : "memory");
}

__device__ __forceinline__ void grid_sync(unsigned gen) {
    __syncthreads();
    if (threadIdx.x == 0) red_rel_add(&g_cnt[blockIdx.x & 15], 1u);
    if (threadIdx.x < 16) {
        while (ld_acq(&g_cnt[threadIdx.x]) < 8u * gen) { }
    }
    __syncthreads();
}

__global__ void k_reset() {
    if (threadIdx.x < 16) g_cnt[threadIdx.x] = 0;
}

// ---------------------------------------------------------------------------
// HMMA + ldmatrix + cp.async + helpers
// ---------------------------------------------------------------------------
#define MMA(d, a0, a1, a2, a3, b0, b1)                                        \
    asm volatile("mma.sync.aligned.m16n8k16.row.col.f32.bf16.bf16.f32 "       \
        "{%0,%1,%2,%3}, {%4,%5,%6,%7}, {%8,%9}, {%0,%1,%2,%3};"               \
        : "+f"((d)[0]), "+f"((d)[1]), "+f"((d)[2]), "+f"((d)[3])              \
        : "r"(a0), "r"(a1), "r"(a2), "r"(a3), "r"(b0), "r"(b1))

#define LDMX4(r, addr)                                                        \
    asm volatile("ldmatrix.sync.aligned.m8n8.x4.shared.b16 {%0,%1,%2,%3}, [%4];" \
        : "=r"((r)[0]), "=r"((r)[1]), "=r"((r)[2]), "=r"((r)[3]) : "r"(addr))

#define CPASYNC(dst, src) \
    asm volatile("cp.async.cg.shared.global [%0], [%1], 16;" :: "r"(dst), "l"(src) : "memory")
#define CPCOMMIT() asm volatile("cp.async.commit_group;" ::: "memory")
#define CPWAIT(n)  asm volatile("cp.async.wait_group %0;" :: "n"(n) : "memory")

#define BAR_SYNC(id, cnt) \
    asm volatile("bar.sync %0, %1;" :: "r"(id), "r"(cnt) : "memory")

__device__ __forceinline__ void split2(float x0, float x1, uint32_t& hi, uint32_t& lo) {
    __nv_bfloat16 h0 = __float2bfloat16_rn(x0);
    __nv_bfloat16 h1 = __float2bfloat16_rn(x1);
    __nv_bfloat16 l0 = __float2bfloat16_rn(x0 - __bfloat162float(h0));
    __nv_bfloat16 l1 = __float2bfloat16_rn(x1 - __bfloat162float(h1));
    hi = ((uint32_t)__bfloat16_as_ushort(h1) << 16) | (uint32_t)__bfloat16_as_ushort(h0);
    lo = ((uint32_t)__bfloat16_as_ushort(l1) << 16) | (uint32_t)__bfloat16_as_ushort(l0);
}

__device__ __forceinline__ uint32_t smem_u32(const void* p) {
    uint32_t a;
    asm("{ .reg .u64 t; cvta.to.shared.u64 t, %1; cvt.u32.u64 %0, t; }" : "=r"(a) : "l"(p));
    return a;
}

__device__ __forceinline__ float fast_sigmoid(float x) {
    return __fdividef(1.0f, 1.0f + __expf(-x));
}
__device__ __forceinline__ float fast_tanh(float x) {
    float ax = fabsf(x);
    float e  = __expf(ax + ax);
    float r  = 1.0f - __fdividef(2.0f, e + 1.0f);
    return copysignf(r, x);
}

// ---------------------------------------------------------------------------
// K0: convert fp32 -> bf16 hi/lo once. which: 0 = X, 1..3 = W_{f,o,c}
// ---------------------------------------------------------------------------
__global__ __launch_bounds__(256) void k_conv(const float* __restrict__ src,
                                              int which, int n4) {
    __nv_bfloat16* dhi = (which == 0) ? g_xb_hi : g_wb_hi[which - 1];
    __nv_bfloat16* dlo = (which == 0) ? g_xb_lo : g_wb_lo[which - 1];
    int stride = gridDim.x * 256;
    for (int q = blockIdx.x * 256 + threadIdx.x; q < n4; q += stride) {
        float4 v = ((const float4*)src)[q];
        uint32_t h0, l0, h1, l1;
        split2(v.x, v.y, h0, l0);
        split2(v.z, v.w, h1, l1);
        ((uint2*)dhi)[q] = make_uint2(h0, h1);
        ((uint2*)dlo)[q] = make_uint2(l0, l1);
    }
}

// ---------------------------------------------------------------------------
// K1: input-side GEMM, HMMA bf16 3-term split, cp.async double-buffered.
// M = 32768, N = 3x1024, K = 1024. CTA 128x128, k-step 32, 8 warps (2m x 4n).
// Dynamic SMEM: 2 stages x 4 arrays x 128 x IPITCH bf16 = 80 KB, 2 CTAs/SM.
// ---------------------------------------------------------------------------
#define IPITCH 40
#define IN_ABYTES (128 * IPITCH * 2)          // one array, one stage: 10240 B
#define IN_STG    (4 * IN_ABYTES)             // stage stride: 40960 B
#define SMEM_IN   (2 * IN_STG)                // 81920 B

__global__ __launch_bounds__(256, 2) void k_ingemm(
    const float* __restrict__ bf, const float* __restrict__ bo, const float* __restrict__ bc)
{
    extern __shared__ char ism[];
    const uint32_t sb = smem_u32(ism);

    const int bm = blockIdx.x;
    const int bn = blockIdx.y;
    const int g  = bn >> 3;
    const int col0 = (bn & 7) << 7;

    const float* bg = (g == 0) ? bf : (g == 1) ? bo : bc;

    const int tid  = threadIdx.x;
    const int wid  = tid >> 5;
    const int lane = tid & 31;
    const int gq   = lane >> 2;
    const int tg   = lane & 3;
    const int wm   = wid >> 2;
    const int wn   = wid & 3;

    const int lr = tid >> 1;
    const int lq = tid & 1;

    const __nv_bfloat16* srcs[4] = {
        g_xb_hi + (size_t)(bm * 128 + lr) * II,
        g_xb_lo + (size_t)(bm * 128 + lr) * II,
        g_wb_hi[g] + (size_t)(col0 + lr) * II,
        g_wb_lo[g] + (size_t)(col0 + lr) * II
    };
    uint32_t dsts[4][2];
    #pragma unroll
    for (int a = 0; a < 4; a++)
        #pragma unroll
        for (int j = 0; j < 2; j++) {
            int kb = lq * 16 + j * 8;
            dsts[a][j] = sb + a * IN_ABYTES + (lr * IPITCH + kb) * 2;
        }

    // ldmatrix base addresses (stage 0; add (kt&1)*IN_STG at use)
    const int arow = wm * 64 + (lane & 7) + ((lane >> 3) & 1) * 8;
    const int akc  = ((lane >> 4) & 1) * 8;
    const int brow = wn * 32 + (lane & 7) + ((lane >> 4) & 1) * 8;
    const int bkc  = ((lane >> 3) & 1) * 8;
    uint32_t aHb[4], aLb[4], bHb[2], bLb[2];
    #pragma unroll
    for (int mi = 0; mi < 4; mi++) {
        aHb[mi] = sb + 0 * IN_ABYTES + (((arow + mi * 16) * IPITCH) + akc) * 2;
        aLb[mi] = sb + 1 * IN_ABYTES + (((arow + mi * 16) * IPITCH) + akc) * 2;
    }
    #pragma unroll
    for (int p = 0; p < 2; p++) {
        bHb[p] = sb + 2 * IN_ABYTES + (((brow + p * 16) * IPITCH) + bkc) * 2;
        bLb[p] = sb + 3 * IN_ABYTES + (((brow + p * 16) * IPITCH) + bkc) * 2;
    }

    float acc[4][4][4] = {};

    // prologue: stage k-tile 0 into buffer 0
    #pragma unroll
    for (int a = 0; a < 4; a++)
        #pragma unroll
        for (int j = 0; j < 2; j++)
            CPASYNC(dsts[a][j], srcs[a] + (lq * 16 + j * 8));
    CPCOMMIT();

    for (int kt = 0; kt < 32; kt++) {
        if (kt + 1 < 32) {
            const int k0n = (kt + 1) * 32;
            const uint32_t so = ((kt + 1) & 1) * IN_STG;
            #pragma unroll
            for (int a = 0; a < 4; a++)
                #pragma unroll
                for (int j = 0; j < 2; j++)
                    CPASYNC(dsts[a][j] + so, srcs[a] + k0n + (lq * 16 + j * 8));
            CPCOMMIT();
            CPWAIT(1);
        } else {
            CPWAIT(0);
        }
        __syncthreads();

        const uint32_t stg = (kt & 1) * IN_STG;
        #pragma unroll
        for (int kk = 0; kk < 2; kk++) {
            const uint32_t ko = stg + kk * 32;
            uint32_t ah[4][4], al[4][4];
            #pragma unroll
            for (int mi = 0; mi < 4; mi++) {
                LDMX4(ah[mi], aHb[mi] + ko);
                LDMX4(al[mi], aLb[mi] + ko);
            }
            #pragma unroll
            for (int p = 0; p < 2; p++) {
                uint32_t bh[4], bl[4];
                LDMX4(bh, bHb[p] + ko);
                LDMX4(bl, bLb[p] + ko);
                #pragma unroll
                for (int q = 0; q < 2; q++) {
                    const int ni = p * 2 + q;
                    #pragma unroll
                    for (int mi = 0; mi < 4; mi++)
                        MMA(acc[mi][ni], ah[mi][0], ah[mi][1], ah[mi][2], ah[mi][3], bh[2*q], bh[2*q+1]);
                    #pragma unroll
                    for (int mi = 0; mi < 4; mi++)
                        MMA(acc[mi][ni], ah[mi][0], ah[mi][1], ah[mi][2], ah[mi][3], bl[2*q], bl[2*q+1]);
                    #pragma unroll
                    for (int mi = 0; mi < 4; mi++)
                        MMA(acc[mi][ni], al[mi][0], al[mi][1], al[mi][2], al[mi][3], bh[2*q], bh[2*q+1]);
                }
            }
        }
        __syncthreads();
    }

    #pragma unroll
    for (int mi = 0; mi < 4; mi++) {
        int row0 = bm * 128 + wm * 64 + mi * 16 + gq;
        int b0_ = row0 >> 9,       s0_ = row0 & 511;
        int b1_ = (row0 + 8) >> 9, s1_ = (row0 + 8) & 511;
        #pragma unroll
        for (int ni = 0; ni < 4; ni++) {
            int col = col0 + wn * 32 + ni * 8 + tg * 2;
            float2 bb = {bg[col], bg[col + 1]};
            *(float2*)&g_xg[g][s0_][b0_][col] = make_float2(acc[mi][ni][0] + bb.x, acc[mi][ni][1] + bb.y);
            *(float2*)&g_xg[g][s1_][b1_][col] = make_float2(acc[mi][ni][2] + bb.x, acc[mi][ni][3] + bb.y);
        }
    }
}

// ---------------------------------------------------------------------------
// K2: persistent HMMA scan. 128 CTAs x 256 thr.
// Per CTA: coltile(32: 32 cols x 3 gates = 96 U-rows) x ksplit(4: K=256).
// Changes vs round 8: barrier v4 (all-CTA poll), pairwise staging sync
// (each warp stages the 8 h-rows its pair reads; named bar.sync id,64).
// ---------------------------------------------------------------------------
#define SPITCH 264
#define OFF_U_HI 0
#define OFF_U_LO (OFF_U_HI + 96 * SPITCH * 2)    //  50688
#define OFF_H_HI (OFF_U_LO + 96 * SPITCH * 2)    // 101376
#define OFF_H_LO (OFF_H_HI + 64 * SPITCH * 2)    // 135168
#define SMEM_SCAN (OFF_H_LO + 64 * SPITCH * 2)   // 168960

__global__ __launch_bounds__(NTHR_SCAN) void k_scan(
    const float* __restrict__ Uf, const float* __restrict__ Uo, const float* __restrict__ Uc,
    float* __restrict__ out)
{
    extern __shared__ char smem[];
    uint16_t* Uh = (uint16_t*)(smem + OFF_U_HI);   // [urow 0..95][SPITCH]
    uint16_t* Ul = (uint16_t*)(smem + OFF_U_LO);

    const int cta  = blockIdx.x;          // 0..127
    const int ct   = cta >> 2;            // coltile 0..31 (32 cols)
    const int ks   = cta & 3;             // ksplit (K=256)
    const int kbeg = ks * KCHUNK;
    const int colbase = ct * 32;

    const int tid  = threadIdx.x;
    const int wid  = tid >> 5;
    const int lane = tid & 31;
    const int gq   = lane >> 2;
    const int tg   = lane & 3;
    const int mi   = wid & 3;             // 16-batch-row block
    const int nj   = wid >> 2;            // 48-urow block (0..1)
    const int gtid = cta * NTHR_SCAN + tid;

    // ---- convert U slice (3 gates x 32 cols x 256 k) to bf16 hi/lo SMEM ----
    const float* Usrc[3] = {Uf, Uo, Uc};
    for (int q = tid; q < 96 * 64; q += NTHR_SCAN) {   // float4 slots
        int urow = q >> 6;
        int g    = urow >> 5;
        int r    = urow & 31;
        int k    = (q & 63) << 2;
        float4 u = *(const float4*)(Usrc[g] + (size_t)(colbase + r) * HH + kbeg + k);
        uint32_t h, l;
        split2(u.x, u.y, h, l);
        *(uint32_t*)&Uh[urow * SPITCH + k]     = h;
        *(uint32_t*)&Ul[urow * SPITCH + k]     = l;
        split2(u.z, u.w, h, l);
        *(uint32_t*)&Uh[urow * SPITCH + k + 2] = h;
        *(uint32_t*)&Ul[urow * SPITCH + k + 2] = l;
    }

    // ---- zero h (graph replays must not inherit state) ----
    for (int i = gtid; i < BB * HH; i += SCAN_THREADS) {
        g_hb_hi[i] = __ushort_as_bfloat16(0);
        g_hb_lo[i] = __ushort_as_bfloat16(0);
    }

    // ---- per-thread ldmatrix base addresses ----
    const uint32_t sb = smem_u32(smem);
    const int arow = mi * 16 + (lane & 7) + ((lane >> 3) & 1) * 8;
    const int akc  = ((lane >> 4) & 1) * 8;
    const uint32_t aH = sb + OFF_H_HI + (arow * SPITCH + akc) * 2;
    const uint32_t aL = sb + OFF_H_LO + (arow * SPITCH + akc) * 2;
    const int brow = (lane & 7) + ((lane >> 4) & 1) * 8;
    const int bkc  = ((lane >> 3) & 1) * 8;
    uint32_t bH[3], bL[3];
    #pragma unroll
    for (int j = 0; j < 3; j++) {
        int r = nj * 48 + j * 16 + brow;
        bH[j] = sb + OFF_U_HI + (r * SPITCH + bkc) * 2;
        bL[j] = sb + OFF_U_LO + (r * SPITCH + bkc) * 2;
    }

    const int b0_ = mi * 16 + gq;
    const int b1_ = b0_ + 8;

    // staging: this warp owns h-rows [rowbase, rowbase+8) (pair = mi)
    const int rowbase = mi * 16 + nj * 8;

    // phase B fixed mapping: this thread owns (pb_b, pb_col..pb_col+1); c in regs
    const int pb_b   = gtid >> 9;
    const int pb_col = (gtid & 511) << 1;
    float cc0 = 0.0f, cc1 = 0.0f;

    unsigned gen = 1;
    grid_sync(gen++);

    for (int t = 0; t < SS; t++) {
        // ---- stage this pair's h rows (8 rows x 256 bf16, hi+lo) ----
        #pragma unroll
        for (int i = 0; i < 8; i++) {
            int row = rowbase + i;
            const char* sh = (const char*)g_hb_hi + (size_t)row * 2048 + kbeg * 2;
            const char* sl = (const char*)g_hb_lo + (size_t)row * 2048 + kbeg * 2;
            *(uint4*)(smem + OFF_H_HI + row * (SPITCH * 2) + lane * 16) =
                ((const uint4*)sh)[lane];
            *(uint4*)(smem + OFF_H_LO + row * (SPITCH * 2) + lane * 16) =
                ((const uint4*)sl)[lane];
        }
        BAR_SYNC(mi + 1, 64);             // pair barrier: warps mi and mi+4

        // ---- HMMA: D[16 b][48 urows] per warp, K=256, 3-term split ----
        float acc[6][4] = {};
        #pragma unroll 2
        for (int kk = 0; kk < 16; kk++) {
            const uint32_t ko = kk * 32;
            uint32_t a_h[4], a_l[4];
            LDMX4(a_h, aH + ko);
            LDMX4(a_l, aL + ko);
            #pragma unroll
            for (int j = 0; j < 3; j++) {
                uint32_t bh[4], bl[4];
                LDMX4(bh, bH[j] + ko);
                LDMX4(bl, bL[j] + ko);
                MMA(acc[j*2],   a_h[0], a_h[1], a_h[2], a_h[3], bh[0], bh[1]);
                MMA(acc[j*2],   a_h[0], a_h[1], a_h[2], a_h[3], bl[0], bl[1]);
                MMA(acc[j*2],   a_l[0], a_l[1], a_l[2], a_l[3], bh[0], bh[1]);
                MMA(acc[j*2+1], a_h[0], a_h[1], a_h[2], a_h[3], bh[2], bh[3]);
                MMA(acc[j*2+1], a_h[0], a_h[1], a_h[2], a_h[3], bl[2], bl[3]);
                MMA(acc[j*2+1], a_l[0], a_l[1], a_l[2], a_l[3], bh[2], bh[3]);
            }
        }

        // ---- write partials: urow -> (gate, col) ----
        #pragma unroll
        for (int idx = 0; idx < 6; idx++) {
            int n    = nj * 48 + idx * 8 + tg * 2;
            int g    = n >> 5;
            int col  = colbase + (n & 31);
            *(float2*)&g_part[ks][g][b0_][col] = make_float2(acc[idx][0], acc[idx][1]);
            *(float2*)&g_part[ks][g][b1_][col] = make_float2(acc[idx][2], acc[idx][3]);
        }

        // ---- prefetch phase-B gate pre-activations (complete during barrier)
        float2 xf = *(const float2*)&g_xg[0][t][pb_b][pb_col];
        float2 xo = *(const float2*)&g_xg[1][t][pb_b][pb_col];
        float2 xc = *(const float2*)&g_xg[2][t][pb_b][pb_col];

        grid_sync(gen++);

        // ---- phase B: all 32768 threads, float2 each, c in registers ----
        {
            float pf0 = xf.x, pf1 = xf.y;
            float po0 = xo.x, po1 = xo.y;
            float pc0 = xc.x, pc1 = xc.y;
            #pragma unroll
            for (int k = 0; k < KSPLIT; k++) {
                float2 v;
                v = *(const float2*)&g_part[k][0][pb_b][pb_col];
                pf0 += v.x; pf1 += v.y;
                v = *(const float2*)&g_part[k][1][pb_b][pb_col];
                po0 += v.x; po1 += v.y;
                v = *(const float2*)&g_part[k][2][pb_b][pb_col];
                pc0 += v.x; pc1 += v.y;
            }
            cc0 = fast_sigmoid(pf0) * cc0 + fast_tanh(pc0);
            cc1 = fast_sigmoid(pf1) * cc1 + fast_tanh(pc1);
            float h0 = fast_sigmoid(po0) * cc0;
            float h1 = fast_sigmoid(po1) * cc1;

            uint32_t hh, hl;
            split2(h0, h1, hh, hl);
            *(uint32_t*)&g_hb_hi[pb_b * HH + pb_col] = hh;
            *(uint32_t*)&g_hb_lo[pb_b * HH + pb_col] = hl;

            *(float2*)&out[((size_t)pb_b * SS + t) * HH + pb_col] = make_float2(h0, h1);
            if (t == SS - 1) {
                float* o2 = out + (size_t)BB * SS * HH;
                *(float2*)&o2[pb_b * HH + pb_col] = make_float2(h0, h1);
                float* o3 = o2 + BB * HH;
                *(float2*)&o3[pb_b * HH + pb_col] = make_float2(cc0, cc1);
            }
        }
        grid_sync(gen++);
    }
}

extern "C" void kernel_launch(void* const* d_in, const int* in_sizes, int n_in,
                              void* d_out, int out_size) {
    const float* X  = (const float*)d_in[0];
    const float* Wf = (const float*)d_in[1];
    const float* Uf = (const float*)d_in[2];
    const float* bf = (const float*)d_in[3];
    // d_in[4..6] = W_i/U_i/b_i: gate i is computed-but-unused in the reference.
    const float* Wo = (const float*)d_in[7];
    const float* Uo = (const float*)d_in[8];
    const float* bo = (const float*)d_in[9];
    const float* Wc = (const float*)d_in[10];
    const float* Uc = (const float*)d_in[11];
    const float* bc = (const float*)d_in[12];
    float* out = (float*)d_out;

    cudaFuncSetAttribute(k_ingemm, cudaFuncAttributeMaxDynamicSharedMemorySize, SMEM_IN);
    cudaFuncSetAttribute(k_scan, cudaFuncAttributeMaxDynamicSharedMemorySize, SMEM_SCAN);

    k_reset<<<1, 32>>>();
    k_conv<<<4096, 256>>>(X,  0, (BB * SS * II) / 4);
    k_conv<<<1024, 256>>>(Wf, 1, (HH * II) / 4);
    k_conv<<<1024, 256>>>(Wo, 2, (HH * II) / 4);
    k_conv<<<1024, 256>>>(Wc, 3, (HH * II) / 4);
    k_ingemm<<<dim3(256, 24), 256, SMEM_IN>>>(bf, bo, bc);
    k_scan<<<NCTA_SCAN, NTHR_SCAN, SMEM_SCAN>>>(Uf, Uo, Uc, out);
}

// round 10
// speedup vs baseline: 1.9145x; 1.0296x over previous
#include <cuda_runtime.h>
#include <cuda_bf16.h>
#include <math.h>
#include <stdint.h>

#define BB 64
#define SS 512
#define II 1024
#define HH 1024

#define KSPLIT 4                 // scan K-splits (chunk = 256)
#define KCHUNK 256
#define NCTA_SCAN 128            // 32 coltiles (32 cols x 3 gates) x 4 ksplits
#define NTHR_SCAN 256
#define SCAN_THREADS (NCTA_SCAN * NTHR_SCAN)

// ---------------------------------------------------------------------------
// Device globals (no allocation allowed anywhere)
// ---------------------------------------------------------------------------
__device__ float g_xg[3][SS][BB][HH];           // input-side pre-activations
__device__ float g_part[KSPLIT][3][BB][HH];     // recurrent GEMM partials
__device__ __nv_bfloat16 g_hb_hi[BB * HH];      // h split into bf16 hi/lo
__device__ __nv_bfloat16 g_hb_lo[BB * HH];
__device__ __nv_bfloat16 g_xb_hi[BB * SS * II]; // X pre-split to bf16 hi/lo
__device__ __nv_bfloat16 g_xb_lo[BB * SS * II];
__device__ __nv_bfloat16 g_wb_hi[3][HH * II];   // W_f/o/c pre-split
__device__ __nv_bfloat16 g_wb_lo[3][HH * II];

// grid barrier: 16 arrival buckets (8 CTAs each); every CTA polls all buckets
__device__ unsigned g_cnt[16];
// per-coltile group flags (4 CTAs per group arrive once per step)
__device__ unsigned g_flag[32];

__device__ __forceinline__ unsigned ld_acq(const unsigned* p) {
    unsigned v;
    asm volatile("ld.acquire.gpu.global.u32 %0, [%1];" : "=r"(v) : "l"(p));
    return v;
}
__device__ __forceinline__ void red_rel_add(unsigned* p, unsigned v) {
    asm volatile("red.release.gpu.global.add.u32 [%0], %1;" :: "l"(p), "r"(v) : "memory");
}

__device__ __forceinline__ void grid_sync(unsigned gen) {
    __syncthreads();
    if (threadIdx.x == 0) red_rel_add(&g_cnt[blockIdx.x & 15], 1u);
    if (threadIdx.x < 16) {
        while (ld_acq(&g_cnt[threadIdx.x]) < 8u * gen) { }
    }
    __syncthreads();
}

__global__ void k_reset() {
    if (threadIdx.x < 16) g_cnt[threadIdx.x] = 0;
    if (threadIdx.x < 32) g_flag[threadIdx.x] = 0;
}

// ---------------------------------------------------------------------------
// HMMA + ldmatrix + cp.async + helpers
// ---------------------------------------------------------------------------
#define MMA(d, a0, a1, a2, a3, b0, b1)                                        \
    asm volatile("mma.sync.aligned.m16n8k16.row.col.f32.bf16.bf16.f32 "       \
        "{%0,%1,%2,%3}, {%4,%5,%6,%7}, {%8,%9}, {%0,%1,%2,%3};"               \
        : "+f"((d)[0]), "+f"((d)[1]), "+f"((d)[2]), "+f"((d)[3])              \
        : "r"(a0), "r"(a1), "r"(a2), "r"(a3), "r"(b0), "r"(b1))

#define LDMX4(r, addr)                                                        \
    asm volatile("ldmatrix.sync.aligned.m8n8.x4.shared.b16 {%0,%1,%2,%3}, [%4];" \
        : "=r"((r)[0]), "=r"((r)[1]), "=r"((r)[2]), "=r"((r)[3]) : "r"(addr))

#define CPASYNC(dst, src) \
    asm volatile("cp.async.cg.shared.global [%0], [%1], 16;" :: "r"(dst), "l"(src) : "memory")
#define CPCOMMIT() asm volatile("cp.async.commit_group;" ::: "memory")
#define CPWAIT(n)  asm volatile("cp.async.wait_group %0;" :: "n"(n) : "memory")

#define BAR_SYNC(id, cnt) \
    asm volatile("bar.sync %0, %1;" :: "r"(id), "r"(cnt) : "memory")

__device__ __forceinline__ void split2(float x0, float x1, uint32_t& hi, uint32_t& lo) {
    __nv_bfloat16 h0 = __float2bfloat16_rn(x0);
    __nv_bfloat16 h1 = __float2bfloat16_rn(x1);
    __nv_bfloat16 l0 = __float2bfloat16_rn(x0 - __bfloat162float(h0));
    __nv_bfloat16 l1 = __float2bfloat16_rn(x1 - __bfloat162float(h1));
    hi = ((uint32_t)__bfloat16_as_ushort(h1) << 16) | (uint32_t)__bfloat16_as_ushort(h0);
    lo = ((uint32_t)__bfloat16_as_ushort(l1) << 16) | (uint32_t)__bfloat16_as_ushort(l0);
}

__device__ __forceinline__ uint32_t smem_u32(const void* p) {
    uint32_t a;
    asm("{ .reg .u64 t; cvta.to.shared.u64 t, %1; cvt.u32.u64 %0, t; }" : "=r"(a) : "l"(p));
    return a;
}

__device__ __forceinline__ float fast_sigmoid(float x) {
    return __fdividef(1.0f, 1.0f + __expf(-x));
}
__device__ __forceinline__ float fast_tanh(float x) {
    float ax = fabsf(x);
    float e  = __expf(ax + ax);
    float r  = 1.0f - __fdividef(2.0f, e + 1.0f);
    return copysignf(r, x);
}

// ---------------------------------------------------------------------------
// K0: convert fp32 -> bf16 hi/lo once. which: 0 = X, 1..3 = W_{f,o,c}
// ---------------------------------------------------------------------------
__global__ __launch_bounds__(256) void k_conv(const float* __restrict__ src,
                                              int which, int n4) {
    __nv_bfloat16* dhi = (which == 0) ? g_xb_hi : g_wb_hi[which - 1];
    __nv_bfloat16* dlo = (which == 0) ? g_xb_lo : g_wb_lo[which - 1];
    int stride = gridDim.x * 256;
    for (int q = blockIdx.x * 256 + threadIdx.x; q < n4; q += stride) {
        float4 v = ((const float4*)src)[q];
        uint32_t h0, l0, h1, l1;
        split2(v.x, v.y, h0, l0);
        split2(v.z, v.w, h1, l1);
        ((uint2*)dhi)[q] = make_uint2(h0, h1);
        ((uint2*)dlo)[q] = make_uint2(l0, l1);
    }
}

// ---------------------------------------------------------------------------
// K1: input-side GEMM, HMMA bf16 3-term split, cp.async double-buffered.
// (identical to round 9)
// ---------------------------------------------------------------------------
#define IPITCH 40
#define IN_ABYTES (128 * IPITCH * 2)          // one array, one stage: 10240 B
#define IN_STG    (4 * IN_ABYTES)             // stage stride: 40960 B
#define SMEM_IN   (2 * IN_STG)                // 81920 B

__global__ __launch_bounds__(256, 2) void k_ingemm(
    const float* __restrict__ bf, const float* __restrict__ bo, const float* __restrict__ bc)
{
    extern __shared__ char ism[];
    const uint32_t sb = smem_u32(ism);

    const int bm = blockIdx.x;
    const int bn = blockIdx.y;
    const int g  = bn >> 3;
    const int col0 = (bn & 7) << 7;

    const float* bg = (g == 0) ? bf : (g == 1) ? bo : bc;

    const int tid  = threadIdx.x;
    const int wid  = tid >> 5;
    const int lane = tid & 31;
    const int gq   = lane >> 2;
    const int tg   = lane & 3;
    const int wm   = wid >> 2;
    const int wn   = wid & 3;

    const int lr = tid >> 1;
    const int lq = tid & 1;

    const __nv_bfloat16* srcs[4] = {
        g_xb_hi + (size_t)(bm * 128 + lr) * II,
        g_xb_lo + (size_t)(bm * 128 + lr) * II,
        g_wb_hi[g] + (size_t)(col0 + lr) * II,
        g_wb_lo[g] + (size_t)(col0 + lr) * II
    };
    uint32_t dsts[4][2];
    #pragma unroll
    for (int a = 0; a < 4; a++)
        #pragma unroll
        for (int j = 0; j < 2; j++) {
            int kb = lq * 16 + j * 8;
            dsts[a][j] = sb + a * IN_ABYTES + (lr * IPITCH + kb) * 2;
        }

    const int arow = wm * 64 + (lane & 7) + ((lane >> 3) & 1) * 8;
    const int akc  = ((lane >> 4) & 1) * 8;
    const int brow = wn * 32 + (lane & 7) + ((lane >> 4) & 1) * 8;
    const int bkc  = ((lane >> 3) & 1) * 8;
    uint32_t aHb[4], aLb[4], bHb[2], bLb[2];
    #pragma unroll
    for (int mi = 0; mi < 4; mi++) {
        aHb[mi] = sb + 0 * IN_ABYTES + (((arow + mi * 16) * IPITCH) + akc) * 2;
        aLb[mi] = sb + 1 * IN_ABYTES + (((arow + mi * 16) * IPITCH) + akc) * 2;
    }
    #pragma unroll
    for (int p = 0; p < 2; p++) {
        bHb[p] = sb + 2 * IN_ABYTES + (((brow + p * 16) * IPITCH) + bkc) * 2;
        bLb[p] = sb + 3 * IN_ABYTES + (((brow + p * 16) * IPITCH) + bkc) * 2;
    }

    float acc[4][4][4] = {};

    #pragma unroll
    for (int a = 0; a < 4; a++)
        #pragma unroll
        for (int j = 0; j < 2; j++)
            CPASYNC(dsts[a][j], srcs[a] + (lq * 16 + j * 8));
    CPCOMMIT();

    for (int kt = 0; kt < 32; kt++) {
        if (kt + 1 < 32) {
            const int k0n = (kt + 1) * 32;
            const uint32_t so = ((kt + 1) & 1) * IN_STG;
            #pragma unroll
            for (int a = 0; a < 4; a++)
                #pragma unroll
                for (int j = 0; j < 2; j++)
                    CPASYNC(dsts[a][j] + so, srcs[a] + k0n + (lq * 16 + j * 8));
            CPCOMMIT();
            CPWAIT(1);
        } else {
            CPWAIT(0);
        }
        __syncthreads();

        const uint32_t stg = (kt & 1) * IN_STG;
        #pragma unroll
        for (int kk = 0; kk < 2; kk++) {
            const uint32_t ko = stg + kk * 32;
            uint32_t ah[4][4], al[4][4];
            #pragma unroll
            for (int mi = 0; mi < 4; mi++) {
                LDMX4(ah[mi], aHb[mi] + ko);
                LDMX4(al[mi], aLb[mi] + ko);
            }
            #pragma unroll
            for (int p = 0; p < 2; p++) {
                uint32_t bh[4], bl[4];
                LDMX4(bh, bHb[p] + ko);
                LDMX4(bl, bLb[p] + ko);
                #pragma unroll
                for (int q = 0; q < 2; q++) {
                    const int ni = p * 2 + q;
                    #pragma unroll
                    for (int mi = 0; mi < 4; mi++)
                        MMA(acc[mi][ni], ah[mi][0], ah[mi][1], ah[mi][2], ah[mi][3], bh[2*q], bh[2*q+1]);
                    #pragma unroll
                    for (int mi = 0; mi < 4; mi++)
                        MMA(acc[mi][ni], ah[mi][0], ah[mi][1], ah[mi][2], ah[mi][3], bl[2*q], bl[2*q+1]);
                    #pragma unroll
                    for (int mi = 0; mi < 4; mi++)
                        MMA(acc[mi][ni], al[mi][0], al[mi][1], al[mi][2], al[mi][3], bh[2*q], bh[2*q+1]);
                }
            }
        }
        __syncthreads();
    }

    #pragma unroll
    for (int mi = 0; mi < 4; mi++) {
        int row0 = bm * 128 + wm * 64 + mi * 16 + gq;
        int b0_ = row0 >> 9,       s0_ = row0 & 511;
        int b1_ = (row0 + 8) >> 9, s1_ = (row0 + 8) & 511;
        #pragma unroll
        for (int ni = 0; ni < 4; ni++) {
            int col = col0 + wn * 32 + ni * 8 + tg * 2;
            float2 bb = {bg[col], bg[col + 1]};
            *(float2*)&g_xg[g][s0_][b0_][col] = make_float2(acc[mi][ni][0] + bb.x, acc[mi][ni][1] + bb.y);
            *(float2*)&g_xg[g][s1_][b1_][col] = make_float2(acc[mi][ni][2] + bb.x, acc[mi][ni][3] + bb.y);
        }
    }
}

// ---------------------------------------------------------------------------
// K2: persistent HMMA scan. 128 CTAs x 256 thr.
// Per CTA: coltile(32: 32 cols x 3 gates = 96 U-rows) x ksplit(4: K=256).
// Changes vs round 9: ONE global barrier per step. Partials->phaseB sync is
// a group-local flag (4 CTAs per coltile); phase B remapped so CTA (ct,ks)
// owns cols [ct*32+ks*8, +8) x all 64 b (c still in registers).
// ---------------------------------------------------------------------------
#define SPITCH 264
#define OFF_U_HI 0
#define OFF_U_LO (OFF_U_HI + 96 * SPITCH * 2)    //  50688
#define OFF_H_HI (OFF_U_LO + 96 * SPITCH * 2)    // 101376
#define OFF_H_LO (OFF_H_HI + 64 * SPITCH * 2)    // 135168
#define SMEM_SCAN (OFF_H_LO + 64 * SPITCH * 2)   // 168960

__global__ __launch_bounds__(NTHR_SCAN) void k_scan(
    const float* __restrict__ Uf, const float* __restrict__ Uo, const float* __restrict__ Uc,
    float* __restrict__ out)
{
    extern __shared__ char smem[];
    uint16_t* Uh = (uint16_t*)(smem + OFF_U_HI);   // [urow 0..95][SPITCH]
    uint16_t* Ul = (uint16_t*)(smem + OFF_U_LO);

    const int cta  = blockIdx.x;          // 0..127
    const int ct   = cta >> 2;            // coltile 0..31 (32 cols)
    const int ks   = cta & 3;             // ksplit (K=256)
    const int kbeg = ks * KCHUNK;
    const int colbase = ct * 32;

    const int tid  = threadIdx.x;
    const int wid  = tid >> 5;
    const int lane = tid & 31;
    const int gq   = lane >> 2;
    const int tg   = lane & 3;
    const int mi   = wid & 3;             // 16-batch-row block
    const int nj   = wid >> 2;            // 48-urow block (0..1)
    const int gtid = cta * NTHR_SCAN + tid;

    // ---- convert U slice (3 gates x 32 cols x 256 k) to bf16 hi/lo SMEM ----
    const float* Usrc[3] = {Uf, Uo, Uc};
    for (int q = tid; q < 96 * 64; q += NTHR_SCAN) {   // float4 slots
        int urow = q >> 6;
        int g    = urow >> 5;
        int r    = urow & 31;
        int k    = (q & 63) << 2;
        float4 u = *(const float4*)(Usrc[g] + (size_t)(colbase + r) * HH + kbeg + k);
        uint32_t h, l;
        split2(u.x, u.y, h, l);
        *(uint32_t*)&Uh[urow * SPITCH + k]     = h;
        *(uint32_t*)&Ul[urow * SPITCH + k]     = l;
        split2(u.z, u.w, h, l);
        *(uint32_t*)&Uh[urow * SPITCH + k + 2] = h;
        *(uint32_t*)&Ul[urow * SPITCH + k + 2] = l;
    }

    // ---- zero h (graph replays must not inherit state) ----
    for (int i = gtid; i < BB * HH; i += SCAN_THREADS) {
        g_hb_hi[i] = __ushort_as_bfloat16(0);
        g_hb_lo[i] = __ushort_as_bfloat16(0);
    }

    // ---- per-thread ldmatrix base addresses ----
    const uint32_t sb = smem_u32(smem);
    const int arow = mi * 16 + (lane & 7) + ((lane >> 3) & 1) * 8;
    const int akc  = ((lane >> 4) & 1) * 8;
    const uint32_t aH = sb + OFF_H_HI + (arow * SPITCH + akc) * 2;
    const uint32_t aL = sb + OFF_H_LO + (arow * SPITCH + akc) * 2;
    const int brow = (lane & 7) + ((lane >> 4) & 1) * 8;
    const int bkc  = ((lane >> 3) & 1) * 8;
    uint32_t bH[3], bL[3];
    #pragma unroll
    for (int j = 0; j < 3; j++) {
        int r = nj * 48 + j * 16 + brow;
        bH[j] = sb + OFF_U_HI + (r * SPITCH + bkc) * 2;
        bL[j] = sb + OFF_U_LO + (r * SPITCH + bkc) * 2;
    }

    const int b0_ = mi * 16 + gq;
    const int b1_ = b0_ + 8;

    // staging: this warp owns h-rows [rowbase, rowbase+8) (pair = mi)
    const int rowbase = mi * 16 + nj * 8;

    // phase B: CTA (ct,ks) owns cols [colbase+ks*8, +8) x all 64 b.
    // thread -> (b = tid>>2, col pair = tid&3); c in registers.
    const int pb_b   = tid >> 2;
    const int pb_col = colbase + ks * 8 + (tid & 3) * 2;
    float cc0 = 0.0f, cc1 = 0.0f;

    unsigned gen = 1;
    grid_sync(gen++);

    for (int t = 0; t < SS; t++) {
        // ---- stage this pair's h rows (8 rows x 256 bf16, hi+lo) ----
        #pragma unroll
        for (int i = 0; i < 8; i++) {
            int row = rowbase + i;
            const char* sh = (const char*)g_hb_hi + (size_t)row * 2048 + kbeg * 2;
            const char* sl = (const char*)g_hb_lo + (size_t)row * 2048 + kbeg * 2;
            *(uint4*)(smem + OFF_H_HI + row * (SPITCH * 2) + lane * 16) =
                ((const uint4*)sh)[lane];
            *(uint4*)(smem + OFF_H_LO + row * (SPITCH * 2) + lane * 16) =
                ((const uint4*)sl)[lane];
        }
        BAR_SYNC(mi + 1, 64);             // pair barrier: warps mi and mi+4

        // ---- HMMA: D[16 b][48 urows] per warp, K=256, 3-term split ----
        float acc[6][4] = {};
        #pragma unroll 2
        for (int kk = 0; kk < 16; kk++) {
            const uint32_t ko = kk * 32;
            uint32_t a_h[4], a_l[4];
            LDMX4(a_h, aH + ko);
            LDMX4(a_l, aL + ko);
            #pragma unroll
            for (int j = 0; j < 3; j++) {
                uint32_t bh[4], bl[4];
                LDMX4(bh, bH[j] + ko);
                LDMX4(bl, bL[j] + ko);
                MMA(acc[j*2],   a_h[0], a_h[1], a_h[2], a_h[3], bh[0], bh[1]);
                MMA(acc[j*2],   a_h[0], a_h[1], a_h[2], a_h[3], bl[0], bl[1]);
                MMA(acc[j*2],   a_l[0], a_l[1], a_l[2], a_l[3], bh[0], bh[1]);
                MMA(acc[j*2+1], a_h[0], a_h[1], a_h[2], a_h[3], bh[2], bh[3]);
                MMA(acc[j*2+1], a_h[0], a_h[1], a_h[2], a_h[3], bl[2], bl[3]);
                MMA(acc[j*2+1], a_l[0], a_l[1], a_l[2], a_l[3], bh[2], bh[3]);
            }
        }

        // ---- write partials: urow -> (gate, col) ----
        #pragma unroll
        for (int idx = 0; idx < 6; idx++) {
            int n    = nj * 48 + idx * 8 + tg * 2;
            int g    = n >> 5;
            int col  = colbase + (n & 31);
            *(float2*)&g_part[ks][g][b0_][col] = make_float2(acc[idx][0], acc[idx][1]);
            *(float2*)&g_part[ks][g][b1_][col] = make_float2(acc[idx][2], acc[idx][3]);
        }
        __syncthreads();                   // all partial stores done CTA-wide
        if (tid == 0) red_rel_add(&g_flag[ct], 1u);

        // ---- prefetch phase-B gate pre-activations (fly during flag wait)
        float2 xf = *(const float2*)&g_xg[0][t][pb_b][pb_col];
        float2 xo = *(const float2*)&g_xg[1][t][pb_b][pb_col];
        float2 xc = *(const float2*)&g_xg[2][t][pb_b][pb_col];

        // ---- group-local wait: all 4 ksplit CTAs of this coltile done ----
        if (tid == 0) {
            while (ld_acq(&g_flag[ct]) < 4u * (unsigned)(t + 1)) { }
        }
        __syncthreads();

        // ---- phase B: reduce 4 ksplits x 3 gates, update c, write h ----
        {
            float pf0 = xf.x, pf1 = xf.y;
            float po0 = xo.x, po1 = xo.y;
            float pc0 = xc.x, pc1 = xc.y;
            #pragma unroll
            for (int k = 0; k < KSPLIT; k++) {
                float2 v;
                v = *(const float2*)&g_part[k][0][pb_b][pb_col];
                pf0 += v.x; pf1 += v.y;
                v = *(const float2*)&g_part[k][1][pb_b][pb_col];
                po0 += v.x; po1 += v.y;
                v = *(const float2*)&g_part[k][2][pb_b][pb_col];
                pc0 += v.x; pc1 += v.y;
            }
            cc0 = fast_sigmoid(pf0) * cc0 + fast_tanh(pc0);
            cc1 = fast_sigmoid(pf1) * cc1 + fast_tanh(pc1);
            float h0 = fast_sigmoid(po0) * cc0;
            float h1 = fast_sigmoid(po1) * cc1;

            uint32_t hh, hl;
            split2(h0, h1, hh, hl);
            *(uint32_t*)&g_hb_hi[pb_b * HH + pb_col] = hh;
            *(uint32_t*)&g_hb_lo[pb_b * HH + pb_col] = hl;

            *(float2*)&out[((size_t)pb_b * SS + t) * HH + pb_col] = make_float2(h0, h1);
            if (t == SS - 1) {
                float* o2 = out + (size_t)BB * SS * HH;
                *(float2*)&o2[pb_b * HH + pb_col] = make_float2(h0, h1);
                float* o3 = o2 + BB * HH;
                *(float2*)&o3[pb_b * HH + pb_col] = make_float2(cc0, cc1);
            }
        }

        grid_sync(gen++);                  // single global barrier per step
    }
}

extern "C" void kernel_launch(void* const* d_in, const int* in_sizes, int n_in,
                              void* d_out, int out_size) {
    const float* X  = (const float*)d_in[0];
    const float* Wf = (const float*)d_in[1];
    const float* Uf = (const float*)d_in[2];
    const float* bf = (const float*)d_in[3];
    // d_in[4..6] = W_i/U_i/b_i: gate i is computed-but-unused in the reference.
    const float* Wo = (const float*)d_in[7];
    const float* Uo = (const float*)d_in[8];
    const float* bo = (const float*)d_in[9];
    const float* Wc = (const float*)d_in[10];
    const float* Uc = (const float*)d_in[11];
    const float* bc = (const float*)d_in[12];
    float* out = (float*)d_out;

    cudaFuncSetAttribute(k_ingemm, cudaFuncAttributeMaxDynamicSharedMemorySize, SMEM_IN);
    cudaFuncSetAttribute(k_scan, cudaFuncAttributeMaxDynamicSharedMemorySize, SMEM_SCAN);

    k_reset<<<1, 32>>>();
    k_conv<<<4096, 256>>>(X,  0, (BB * SS * II) / 4);
    k_conv<<<1024, 256>>>(Wf, 1, (HH * II) / 4);
    k_conv<<<1024, 256>>>(Wo, 2, (HH * II) / 4);
    k_conv<<<1024, 256>>>(Wc, 3, (HH * II) / 4);
    k_ingemm<<<dim3(256, 24), 256, SMEM_IN>>>(bf, bo, bc);
    k_scan<<<NCTA_SCAN, NTHR_SCAN, SMEM_SCAN>>>(Uf, Uo, Uc, out);
}

// round 11
// speedup vs baseline: 2.2509x; 1.1757x over previous
#include <cuda_runtime.h>
#include <cuda_bf16.h>
#include <cuda_fp16.h>
#include <math.h>
#include <stdint.h>

#define BB 64
#define SS 512
#define II 1024
#define HH 1024

#define KSPLIT 4                 // scan K-splits (chunk = 256)
#define KCHUNK 256
#define NCTA_SCAN 128            // 32 coltiles (32 cols x 3 gates) x 4 ksplits
#define NTHR_SCAN 256
#define SCAN_THREADS (NCTA_SCAN * NTHR_SCAN)

// ---------------------------------------------------------------------------
// Device globals (no allocation allowed anywhere)
// ---------------------------------------------------------------------------
__device__ float g_xg[3][SS][BB][HH];           // input-side pre-activations
__device__ float g_part[KSPLIT][3][BB][HH];     // recurrent GEMM partials
__device__ __half g_hf[BB * HH];                // h as fp16 (single term)
__device__ __nv_bfloat16 g_xb_hi[BB * SS * II]; // X pre-split to bf16 hi/lo
__device__ __nv_bfloat16 g_xb_lo[BB * SS * II];
__device__ __nv_bfloat16 g_wb_hi[3][HH * II];   // W_f/o/c pre-split
__device__ __nv_bfloat16 g_wb_lo[3][HH * II];

// grid barrier: 16 arrival buckets (8 CTAs each); every CTA polls all buckets
__device__ unsigned g_cnt[16];
// per-coltile group flags (4 CTAs per group arrive once per step)
__device__ unsigned g_flag[32];

__device__ __forceinline__ unsigned ld_acq(const unsigned* p) {
    unsigned v;
    asm volatile("ld.acquire.gpu.global.u32 %0, [%1];" : "=r"(v) : "l"(p));
    return v;
}
__device__ __forceinline__ void red_rel_add(unsigned* p, unsigned v) {
    asm volatile("red.release.gpu.global.add.u32 [%0], %1;" :: "l"(p), "r"(v) : "memory");
}

__device__ __forceinline__ void grid_sync(unsigned gen) {
    __syncthreads();
    if (threadIdx.x == 0) red_rel_add(&g_cnt[blockIdx.x & 15], 1u);
    if (threadIdx.x < 16) {
        while (ld_acq(&g_cnt[threadIdx.x]) < 8u * gen) { }
    }
    __syncthreads();
}

__global__ void k_reset() {
    if (threadIdx.x < 16) g_cnt[threadIdx.x] = 0;
    if (threadIdx.x < 32) g_flag[threadIdx.x] = 0;
}

// ---------------------------------------------------------------------------
// HMMA (bf16 + fp16) + ldmatrix + cp.async + helpers
// ---------------------------------------------------------------------------
#define MMA(d, a0, a1, a2, a3, b0, b1)                                        \
    asm volatile("mma.sync.aligned.m16n8k16.row.col.f32.bf16.bf16.f32 "       \
        "{%0,%1,%2,%3}, {%4,%5,%6,%7}, {%8,%9}, {%0,%1,%2,%3};"               \
        : "+f"((d)[0]), "+f"((d)[1]), "+f"((d)[2]), "+f"((d)[3])              \
        : "r"(a0), "r"(a1), "r"(a2), "r"(a3), "r"(b0), "r"(b1))

#define MMAH(d, a0, a1, a2, a3, b0, b1)                                       \
    asm volatile("mma.sync.aligned.m16n8k16.row.col.f32.f16.f16.f32 "         \
        "{%0,%1,%2,%3}, {%4,%5,%6,%7}, {%8,%9}, {%0,%1,%2,%3};"               \
        : "+f"((d)[0]), "+f"((d)[1]), "+f"((d)[2]), "+f"((d)[3])              \
        : "r"(a0), "r"(a1), "r"(a2), "r"(a3), "r"(b0), "r"(b1))

#define LDMX4(r, addr)                                                        \
    asm volatile("ldmatrix.sync.aligned.m8n8.x4.shared.b16 {%0,%1,%2,%3}, [%4];" \
        : "=r"((r)[0]), "=r"((r)[1]), "=r"((r)[2]), "=r"((r)[3]) : "r"(addr))

#define CPASYNC(dst, src) \
    asm volatile("cp.async.cg.shared.global [%0], [%1], 16;" :: "r"(dst), "l"(src) : "memory")
#define CPCOMMIT() asm volatile("cp.async.commit_group;" ::: "memory")
#define CPWAIT(n)  asm volatile("cp.async.wait_group %0;" :: "n"(n) : "memory")

#define BAR_SYNC(id, cnt) \
    asm volatile("bar.sync %0, %1;" :: "r"(id), "r"(cnt) : "memory")

__device__ __forceinline__ void split2(float x0, float x1, uint32_t& hi, uint32_t& lo) {
    __nv_bfloat16 h0 = __float2bfloat16_rn(x0);
    __nv_bfloat16 h1 = __float2bfloat16_rn(x1);
    __nv_bfloat16 l0 = __float2bfloat16_rn(x0 - __bfloat162float(h0));
    __nv_bfloat16 l1 = __float2bfloat16_rn(x1 - __bfloat162float(h1));
    hi = ((uint32_t)__bfloat16_as_ushort(h1) << 16) | (uint32_t)__bfloat16_as_ushort(h0);
    lo = ((uint32_t)__bfloat16_as_ushort(l1) << 16) | (uint32_t)__bfloat16_as_ushort(l0);
}

__device__ __forceinline__ uint32_t smem_u32(const void* p) {
    uint32_t a;
    asm("{ .reg .u64 t; cvta.to.shared.u64 t, %1; cvt.u32.u64 %0, t; }" : "=r"(a) : "l"(p));
    return a;
}

__device__ __forceinline__ float fast_sigmoid(float x) {
    return __fdividef(1.0f, 1.0f + __expf(-x));
}
__device__ __forceinline__ float fast_tanh(float x) {
    float ax = fabsf(x);
    float e  = __expf(ax + ax);
    float r  = 1.0f - __fdividef(2.0f, e + 1.0f);
    return copysignf(r, x);
}

// ---------------------------------------------------------------------------
// K0: convert fp32 -> bf16 hi/lo once. which: 0 = X, 1..3 = W_{f,o,c}
// ---------------------------------------------------------------------------
__global__ __launch_bounds__(256) void k_conv(const float* __restrict__ src,
                                              int which, int n4) {
    __nv_bfloat16* dhi = (which == 0) ? g_xb_hi : g_wb_hi[which - 1];
    __nv_bfloat16* dlo = (which == 0) ? g_xb_lo : g_wb_lo[which - 1];
    int stride = gridDim.x * 256;
    for (int q = blockIdx.x * 256 + threadIdx.x; q < n4; q += stride) {
        float4 v = ((const float4*)src)[q];
        uint32_t h0, l0, h1, l1;
        split2(v.x, v.y, h0, l0);
        split2(v.z, v.w, h1, l1);
        ((uint2*)dhi)[q] = make_uint2(h0, h1);
        ((uint2*)dlo)[q] = make_uint2(l0, l1);
    }
}

// ---------------------------------------------------------------------------
// K1: input-side GEMM, HMMA bf16 3-term split, cp.async double-buffered.
// (identical to round 10 — keeps xg error at ~5e-6)
// ---------------------------------------------------------------------------
#define IPITCH 40
#define IN_ABYTES (128 * IPITCH * 2)
#define IN_STG    (4 * IN_ABYTES)
#define SMEM_IN   (2 * IN_STG)

__global__ __launch_bounds__(256, 2) void k_ingemm(
    const float* __restrict__ bf, const float* __restrict__ bo, const float* __restrict__ bc)
{
    extern __shared__ char ism[];
    const uint32_t sb = smem_u32(ism);

    const int bm = blockIdx.x;
    const int bn = blockIdx.y;
    const int g  = bn >> 3;
    const int col0 = (bn & 7) << 7;

    const float* bg = (g == 0) ? bf : (g == 1) ? bo : bc;

    const int tid  = threadIdx.x;
    const int wid  = tid >> 5;
    const int lane = tid & 31;
    const int gq   = lane >> 2;
    const int tg   = lane & 3;
    const int wm   = wid >> 2;
    const int wn   = wid & 3;

    const int lr = tid >> 1;
    const int lq = tid & 1;

    const __nv_bfloat16* srcs[4] = {
        g_xb_hi + (size_t)(bm * 128 + lr) * II,
        g_xb_lo + (size_t)(bm * 128 + lr) * II,
        g_wb_hi[g] + (size_t)(col0 + lr) * II,
        g_wb_lo[g] + (size_t)(col0 + lr) * II
    };
    uint32_t dsts[4][2];
    #pragma unroll
    for (int a = 0; a < 4; a++)
        #pragma unroll
        for (int j = 0; j < 2; j++) {
            int kb = lq * 16 + j * 8;
            dsts[a][j] = sb + a * IN_ABYTES + (lr * IPITCH + kb) * 2;
        }

    const int arow = wm * 64 + (lane & 7) + ((lane >> 3) & 1) * 8;
    const int akc  = ((lane >> 4) & 1) * 8;
    const int brow = wn * 32 + (lane & 7) + ((lane >> 4) & 1) * 8;
    const int bkc  = ((lane >> 3) & 1) * 8;
    uint32_t aHb[4], aLb[4], bHb[2], bLb[2];
    #pragma unroll
    for (int mi = 0; mi < 4; mi++) {
        aHb[mi] = sb + 0 * IN_ABYTES + (((arow + mi * 16) * IPITCH) + akc) * 2;
        aLb[mi] = sb + 1 * IN_ABYTES + (((arow + mi * 16) * IPITCH) + akc) * 2;
    }
    #pragma unroll
    for (int p = 0; p < 2; p++) {
        bHb[p] = sb + 2 * IN_ABYTES + (((brow + p * 16) * IPITCH) + bkc) * 2;
        bLb[p] = sb + 3 * IN_ABYTES + (((brow + p * 16) * IPITCH) + bkc) * 2;
    }

    float acc[4][4][4] = {};

    #pragma unroll
    for (int a = 0; a < 4; a++)
        #pragma unroll
        for (int j = 0; j < 2; j++)
            CPASYNC(dsts[a][j], srcs[a] + (lq * 16 + j * 8));
    CPCOMMIT();

    for (int kt = 0; kt < 32; kt++) {
        if (kt + 1 < 32) {
            const int k0n = (kt + 1) * 32;
            const uint32_t so = ((kt + 1) & 1) * IN_STG;
            #pragma unroll
            for (int a = 0; a < 4; a++)
                #pragma unroll
                for (int j = 0; j < 2; j++)
                    CPASYNC(dsts[a][j] + so, srcs[a] + k0n + (lq * 16 + j * 8));
            CPCOMMIT();
            CPWAIT(1);
        } else {
            CPWAIT(0);
        }
        __syncthreads();

        const uint32_t stg = (kt & 1) * IN_STG;
        #pragma unroll
        for (int kk = 0; kk < 2; kk++) {
            const uint32_t ko = stg + kk * 32;
            uint32_t ah[4][4], al[4][4];
            #pragma unroll
            for (int mi = 0; mi < 4; mi++) {
                LDMX4(ah[mi], aHb[mi] + ko);
                LDMX4(al[mi], aLb[mi] + ko);
            }
            #pragma unroll
            for (int p = 0; p < 2; p++) {
                uint32_t bh[4], bl[4];
                LDMX4(bh, bHb[p] + ko);
                LDMX4(bl, bLb[p] + ko);
                #pragma unroll
                for (int q = 0; q < 2; q++) {
                    const int ni = p * 2 + q;
                    #pragma unroll
                    for (int mi = 0; mi < 4; mi++)
                        MMA(acc[mi][ni], ah[mi][0], ah[mi][1], ah[mi][2], ah[mi][3], bh[2*q], bh[2*q+1]);
                    #pragma unroll
                    for (int mi = 0; mi < 4; mi++)
                        MMA(acc[mi][ni], ah[mi][0], ah[mi][1], ah[mi][2], ah[mi][3], bl[2*q], bl[2*q+1]);
                    #pragma unroll
                    for (int mi = 0; mi < 4; mi++)
                        MMA(acc[mi][ni], al[mi][0], al[mi][1], al[mi][2], al[mi][3], bh[2*q], bh[2*q+1]);
                }
            }
        }
        __syncthreads();
    }

    #pragma unroll
    for (int mi = 0; mi < 4; mi++) {
        int row0 = bm * 128 + wm * 64 + mi * 16 + gq;
        int b0_ = row0 >> 9,       s0_ = row0 & 511;
        int b1_ = (row0 + 8) >> 9, s1_ = (row0 + 8) & 511;
        #pragma unroll
        for (int ni = 0; ni < 4; ni++) {
            int col = col0 + wn * 32 + ni * 8 + tg * 2;
            float2 bb = {bg[col], bg[col + 1]};
            *(float2*)&g_xg[g][s0_][b0_][col] = make_float2(acc[mi][ni][0] + bb.x, acc[mi][ni][1] + bb.y);
            *(float2*)&g_xg[g][s1_][b1_][col] = make_float2(acc[mi][ni][2] + bb.x, acc[mi][ni][3] + bb.y);
        }
    }
}

// ---------------------------------------------------------------------------
// K2: persistent fp16 HMMA scan. 128 CTAs x 256 thr.
// Per CTA: coltile(32: 32 cols x 3 gates = 96 U-rows) x ksplit(4: K=256).
// Single-term fp16 (h and U quantized once): 96 MMAs/warp/step (was 288),
// half the staging traffic, SMEM 84 KB. Sync structure = round 10.
// ---------------------------------------------------------------------------
#define SPITCH 264
#define OFF_U  0
#define OFF_H  (96 * SPITCH * 2)                 // 50688
#define SMEM_SCAN (OFF_H + 64 * SPITCH * 2)      // 84480

__global__ __launch_bounds__(NTHR_SCAN) void k_scan(
    const float* __restrict__ Uf, const float* __restrict__ Uo, const float* __restrict__ Uc,
    float* __restrict__ out)
{
    extern __shared__ char smem[];
    uint16_t* Usm = (uint16_t*)(smem + OFF_U);     // [urow 0..95][SPITCH]

    const int cta  = blockIdx.x;          // 0..127
    const int ct   = cta >> 2;            // coltile 0..31 (32 cols)
    const int ks   = cta & 3;             // ksplit (K=256)
    const int kbeg = ks * KCHUNK;
    const int colbase = ct * 32;

    const int tid  = threadIdx.x;
    const int wid  = tid >> 5;
    const int lane = tid & 31;
    const int gq   = lane >> 2;
    const int tg   = lane & 3;
    const int mi   = wid & 3;             // 16-batch-row block
    const int nj   = wid >> 2;            // 48-urow block (0..1)
    const int gtid = cta * NTHR_SCAN + tid;

    // ---- convert U slice (3 gates x 32 cols x 256 k) to fp16 SMEM ----
    const float* Usrc[3] = {Uf, Uo, Uc};
    for (int q = tid; q < 96 * 64; q += NTHR_SCAN) {   // float4 slots
        int urow = q >> 6;
        int g    = urow >> 5;
        int r    = urow & 31;
        int k    = (q & 63) << 2;
        float4 u = *(const float4*)(Usrc[g] + (size_t)(colbase + r) * HH + kbeg + k);
        __half2 p0 = __floats2half2_rn(u.x, u.y);
        __half2 p1 = __floats2half2_rn(u.z, u.w);
        *(__half2*)&Usm[urow * SPITCH + k]     = p0;
        *(__half2*)&Usm[urow * SPITCH + k + 2] = p1;
    }

    // ---- zero h (graph replays must not inherit state) ----
    for (int i = gtid; i < BB * HH; i += SCAN_THREADS)
        g_hf[i] = __ushort_as_half((unsigned short)0);

    // ---- per-thread ldmatrix base addresses ----
    const uint32_t sb = smem_u32(smem);
    const int arow = mi * 16 + (lane & 7) + ((lane >> 3) & 1) * 8;
    const int akc  = ((lane >> 4) & 1) * 8;
    const uint32_t aB = sb + OFF_H + (arow * SPITCH + akc) * 2;
    const int brow = (lane & 7) + ((lane >> 4) & 1) * 8;
    const int bkc  = ((lane >> 3) & 1) * 8;
    uint32_t bB[3];
    #pragma unroll
    for (int j = 0; j < 3; j++) {
        int r = nj * 48 + j * 16 + brow;
        bB[j] = sb + OFF_U + (r * SPITCH + bkc) * 2;
    }

    const int b0_ = mi * 16 + gq;
    const int b1_ = b0_ + 8;

    // staging: this warp owns h-rows [rowbase, rowbase+8)
    const int rowbase = mi * 16 + nj * 8;

    // phase B: CTA (ct,ks) owns cols [colbase+ks*8, +8) x all 64 b; c in regs
    const int pb_b   = tid >> 2;
    const int pb_col = colbase + ks * 8 + (tid & 3) * 2;
    float cc0 = 0.0f, cc1 = 0.0f;

    unsigned gen = 1;
    grid_sync(gen++);

    for (int t = 0; t < SS; t++) {
        // ---- stage this pair's h rows (8 rows x 256 fp16) ----
        #pragma unroll
        for (int i = 0; i < 8; i++) {
            int row = rowbase + i;
            const char* sh = (const char*)g_hf + (size_t)row * (HH * 2) + kbeg * 2;
            *(uint4*)(smem + OFF_H + row * (SPITCH * 2) + lane * 16) =
                ((const uint4*)sh)[lane];
        }
        BAR_SYNC(mi + 1, 64);             // pair barrier: warps mi and mi+4

        // ---- HMMA: D[16 b][48 urows] per warp, K=256, single fp16 term ----
        float acc[6][4] = {};
        #pragma unroll 4
        for (int kk = 0; kk < 16; kk++) {
            const uint32_t ko = kk * 32;
            uint32_t a[4];
            LDMX4(a, aB + ko);
            #pragma unroll
            for (int j = 0; j < 3; j++) {
                uint32_t b[4];
                LDMX4(b, bB[j] + ko);
                MMAH(acc[j*2],   a[0], a[1], a[2], a[3], b[0], b[1]);
                MMAH(acc[j*2+1], a[0], a[1], a[2], a[3], b[2], b[3]);
            }
        }

        // ---- write partials: urow -> (gate, col) ----
        #pragma unroll
        for (int idx = 0; idx < 6; idx++) {
            int n    = nj * 48 + idx * 8 + tg * 2;
            int g    = n >> 5;
            int col  = colbase + (n & 31);
            *(float2*)&g_part[ks][g][b0_][col] = make_float2(acc[idx][0], acc[idx][1]);
            *(float2*)&g_part[ks][g][b1_][col] = make_float2(acc[idx][2], acc[idx][3]);
        }
        __syncthreads();                   // all partial stores done CTA-wide
        if (tid == 0) red_rel_add(&g_flag[ct], 1u);

        // ---- prefetch phase-B gate pre-activations (fly during flag wait)
        float2 xf = *(const float2*)&g_xg[0][t][pb_b][pb_col];
        float2 xo = *(const float2*)&g_xg[1][t][pb_b][pb_col];
        float2 xc = *(const float2*)&g_xg[2][t][pb_b][pb_col];

        // ---- group-local wait: all 4 ksplit CTAs of this coltile done ----
        if (tid == 0) {
            while (ld_acq(&g_flag[ct]) < 4u * (unsigned)(t + 1)) { }
        }
        __syncthreads();

        // ---- phase B: reduce 4 ksplits x 3 gates, update c, write h ----
        {
            float pf0 = xf.x, pf1 = xf.y;
            float po0 = xo.x, po1 = xo.y;
            float pc0 = xc.x, pc1 = xc.y;
            #pragma unroll
            for (int k = 0; k < KSPLIT; k++) {
                float2 v;
                v = *(const float2*)&g_part[k][0][pb_b][pb_col];
                pf0 += v.x; pf1 += v.y;
                v = *(const float2*)&g_part[k][1][pb_b][pb_col];
                po0 += v.x; po1 += v.y;
                v = *(const float2*)&g_part[k][2][pb_b][pb_col];
                pc0 += v.x; pc1 += v.y;
            }
            cc0 = fast_sigmoid(pf0) * cc0 + fast_tanh(pc0);
            cc1 = fast_sigmoid(pf1) * cc1 + fast_tanh(pc1);
            float h0 = fast_sigmoid(po0) * cc0;
            float h1 = fast_sigmoid(po1) * cc1;

            *(__half2*)&g_hf[pb_b * HH + pb_col] = __floats2half2_rn(h0, h1);

            *(float2*)&out[((size_t)pb_b * SS + t) * HH + pb_col] = make_float2(h0, h1);
            if (t == SS - 1) {
                float* o2 = out + (size_t)BB * SS * HH;
                *(float2*)&o2[pb_b * HH + pb_col] = make_float2(h0, h1);
                float* o3 = o2 + BB * HH;
                *(float2*)&o3[pb_b * HH + pb_col] = make_float2(cc0, cc1);
            }
        }

        grid_sync(gen++);                  // single global barrier per step
    }
}

extern "C" void kernel_launch(void* const* d_in, const int* in_sizes, int n_in,
                              void* d_out, int out_size) {
    const float* X  = (const float*)d_in[0];
    const float* Wf = (const float*)d_in[1];
    const float* Uf = (const float*)d_in[2];
    const float* bf = (const float*)d_in[3];
    // d_in[4..6] = W_i/U_i/b_i: gate i is computed-but-unused in the reference.
    const float* Wo = (const float*)d_in[7];
    const float* Uo = (const float*)d_in[8];
    const float* bo = (const float*)d_in[9];
    const float* Wc = (const float*)d_in[10];
    const float* Uc = (const float*)d_in[11];
    const float* bc = (const float*)d_in[12];
    float* out = (float*)d_out;

    cudaFuncSetAttribute(k_ingemm, cudaFuncAttributeMaxDynamicSharedMemorySize, SMEM_IN);
    cudaFuncSetAttribute(k_scan, cudaFuncAttributeMaxDynamicSharedMemorySize, SMEM_SCAN);

    k_reset<<<1, 32>>>();
    k_conv<<<4096, 256>>>(X,  0, (BB * SS * II) / 4);
    k_conv<<<1024, 256>>>(Wf, 1, (HH * II) / 4);
    k_conv<<<1024, 256>>>(Wo, 2, (HH * II) / 4);
    k_conv<<<1024, 256>>>(Wc, 3, (HH * II) / 4);
    k_ingemm<<<dim3(256, 24), 256, SMEM_IN>>>(bf, bo, bc);
    k_scan<<<NCTA_SCAN, NTHR_SCAN, SMEM_SCAN>>>(Uf, Uo, Uc, out);
}

// round 12
// speedup vs baseline: 2.8570x; 1.2692x over previous
#include <cuda_runtime.h>
#include <cuda_bf16.h>
#include <cuda_fp16.h>
#include <math.h>
#include <stdint.h>

#define BB 64
#define SS 512
#define II 1024
#define HH 1024

#define KSPLIT 4                 // scan K-splits (chunk = 256)
#define KCHUNK 256
#define NCTA_SCAN 128            // 32 coltiles (32 cols x 3 gates) x 4 ksplits
#define NTHR_SCAN 256
#define SCAN_THREADS (NCTA_SCAN * NTHR_SCAN)

// ---------------------------------------------------------------------------
// Device globals (no allocation allowed anywhere)
// ---------------------------------------------------------------------------
__device__ float g_xg[3][SS][BB][HH];           // input-side pre-activations
__device__ float g_part[KSPLIT][3][BB][HH];     // recurrent GEMM partials
__device__ __half g_hf[BB * HH];                // h as fp16 (single term)
__device__ __half g_xh[BB * SS * II];           // X as fp16 (single term)
__device__ __half g_wh[3][HH * II];             // W_f/o/c as fp16

// grid barrier: 16 arrival buckets (8 CTAs each); every CTA polls all buckets
__device__ unsigned g_cnt[16];
// per-coltile group flags (4 CTAs per group arrive once per step)
__device__ unsigned g_flag[32];

__device__ __forceinline__ unsigned ld_acq(const unsigned* p) {
    unsigned v;
    asm volatile("ld.acquire.gpu.global.u32 %0, [%1];" : "=r"(v) : "l"(p));
    return v;
}
__device__ __forceinline__ void red_rel_add(unsigned* p, unsigned v) {
    asm volatile("red.release.gpu.global.add.u32 [%0], %1;" :: "l"(p), "r"(v) : "memory");
}

__device__ __forceinline__ void grid_sync(unsigned gen) {
    __syncthreads();
    if (threadIdx.x == 0) red_rel_add(&g_cnt[blockIdx.x & 15], 1u);
    if (threadIdx.x < 16) {
        while (ld_acq(&g_cnt[threadIdx.x]) < 8u * gen) { }
    }
    __syncthreads();
}

__global__ void k_reset() {
    if (threadIdx.x < 16) g_cnt[threadIdx.x] = 0;
    if (threadIdx.x < 32) g_flag[threadIdx.x] = 0;
}

// ---------------------------------------------------------------------------
// fp16 HMMA + ldmatrix + cp.async + helpers
// ---------------------------------------------------------------------------
#define MMAH(d, a0, a1, a2, a3, b0, b1)                                       \
    asm volatile("mma.sync.aligned.m16n8k16.row.col.f32.f16.f16.f32 "         \
        "{%0,%1,%2,%3}, {%4,%5,%6,%7}, {%8,%9}, {%0,%1,%2,%3};"               \
        : "+f"((d)[0]), "+f"((d)[1]), "+f"((d)[2]), "+f"((d)[3])              \
        : "r"(a0), "r"(a1), "r"(a2), "r"(a3), "r"(b0), "r"(b1))

#define LDMX4(r, addr)                                                        \
    asm volatile("ldmatrix.sync.aligned.m8n8.x4.shared.b16 {%0,%1,%2,%3}, [%4];" \
        : "=r"((r)[0]), "=r"((r)[1]), "=r"((r)[2]), "=r"((r)[3]) : "r"(addr))

#define CPASYNC(dst, src) \
    asm volatile("cp.async.cg.shared.global [%0], [%1], 16;" :: "r"(dst), "l"(src) : "memory")
#define CPCOMMIT() asm volatile("cp.async.commit_group;" ::: "memory")
#define CPWAIT(n)  asm volatile("cp.async.wait_group %0;" :: "n"(n) : "memory")

#define BAR_SYNC(id, cnt) \
    asm volatile("bar.sync %0, %1;" :: "r"(id), "r"(cnt) : "memory")

__device__ __forceinline__ uint32_t smem_u32(const void* p) {
    uint32_t a;
    asm("{ .reg .u64 t; cvta.to.shared.u64 t, %1; cvt.u32.u64 %0, t; }" : "=r"(a) : "l"(p));
    return a;
}

__device__ __forceinline__ float fast_sigmoid(float x) {
    return __fdividef(1.0f, 1.0f + __expf(-x));
}
__device__ __forceinline__ float fast_tanh(float x) {
    float ax = fabsf(x);
    float e  = __expf(ax + ax);
    float r  = 1.0f - __fdividef(2.0f, e + 1.0f);
    return copysignf(r, x);
}

// ---------------------------------------------------------------------------
// K0: convert fp32 -> fp16 once. which: 0 = X, 1..3 = W_{f,o,c}
// ---------------------------------------------------------------------------
__global__ __launch_bounds__(256) void k_conv(const float* __restrict__ src,
                                              int which, int n4) {
    __half* d = (which == 0) ? g_xh : g_wh[which - 1];
    int stride = gridDim.x * 256;
    for (int q = blockIdx.x * 256 + threadIdx.x; q < n4; q += stride) {
        float4 v = ((const float4*)src)[q];
        __half2 p0 = __floats2half2_rn(v.x, v.y);
        __half2 p1 = __floats2half2_rn(v.z, v.w);
        ((uint2*)d)[q] = make_uint2(*(uint32_t*)&p0, *(uint32_t*)&p1);
    }
}

// ---------------------------------------------------------------------------
// K1: input-side GEMM, single-term fp16 HMMA, cp.async double-buffered.
// M = 32768, N = 3x1024, K = 1024. CTA 128x128, k-step 32, 8 warps (2m x 4n).
// Dynamic SMEM: 2 stages x 2 arrays x 128 x IPITCH fp16 = 40 KB, 2 CTAs/SM.
// ---------------------------------------------------------------------------
#define IPITCH 40
#define IN_ABYTES (128 * IPITCH * 2)          // one array, one stage: 10240 B
#define IN_STG    (2 * IN_ABYTES)             // stage stride: 20480 B
#define SMEM_IN   (2 * IN_STG)                // 40960 B

__global__ __launch_bounds__(256, 2) void k_ingemm(
    const float* __restrict__ bf, const float* __restrict__ bo, const float* __restrict__ bc)
{
    extern __shared__ char ism[];
    const uint32_t sb = smem_u32(ism);

    const int bm = blockIdx.x;
    const int bn = blockIdx.y;
    const int g  = bn >> 3;
    const int col0 = (bn & 7) << 7;

    const float* bg = (g == 0) ? bf : (g == 1) ? bo : bc;

    const int tid  = threadIdx.x;
    const int wid  = tid >> 5;
    const int lane = tid & 31;
    const int gq   = lane >> 2;
    const int tg   = lane & 3;
    const int wm   = wid >> 2;
    const int wn   = wid & 3;

    const int lr = tid >> 1;
    const int lq = tid & 1;

    const __half* srcs[2] = {
        g_xh + (size_t)(bm * 128 + lr) * II,
        g_wh[g] + (size_t)(col0 + lr) * II
    };
    uint32_t dsts[2][2];
    #pragma unroll
    for (int a = 0; a < 2; a++)
        #pragma unroll
        for (int j = 0; j < 2; j++) {
            int kb = lq * 16 + j * 8;
            dsts[a][j] = sb + a * IN_ABYTES + (lr * IPITCH + kb) * 2;
        }

    const int arow = wm * 64 + (lane & 7) + ((lane >> 3) & 1) * 8;
    const int akc  = ((lane >> 4) & 1) * 8;
    const int brow = wn * 32 + (lane & 7) + ((lane >> 4) & 1) * 8;
    const int bkc  = ((lane >> 3) & 1) * 8;
    uint32_t aBb[4], bBb[2];
    #pragma unroll
    for (int mi = 0; mi < 4; mi++)
        aBb[mi] = sb + 0 * IN_ABYTES + (((arow + mi * 16) * IPITCH) + akc) * 2;
    #pragma unroll
    for (int p = 0; p < 2; p++)
        bBb[p] = sb + 1 * IN_ABYTES + (((brow + p * 16) * IPITCH) + bkc) * 2;

    float acc[4][4][4] = {};

    // prologue: stage k-tile 0 into buffer 0
    #pragma unroll
    for (int a = 0; a < 2; a++)
        #pragma unroll
        for (int j = 0; j < 2; j++)
            CPASYNC(dsts[a][j], srcs[a] + (lq * 16 + j * 8));
    CPCOMMIT();

    for (int kt = 0; kt < 32; kt++) {
        if (kt + 1 < 32) {
            const int k0n = (kt + 1) * 32;
            const uint32_t so = ((kt + 1) & 1) * IN_STG;
            #pragma unroll
            for (int a = 0; a < 2; a++)
                #pragma unroll
                for (int j = 0; j < 2; j++)
                    CPASYNC(dsts[a][j] + so, srcs[a] + k0n + (lq * 16 + j * 8));
            CPCOMMIT();
            CPWAIT(1);
        } else {
            CPWAIT(0);
        }
        __syncthreads();

        const uint32_t stg = (kt & 1) * IN_STG;
        #pragma unroll
        for (int kk = 0; kk < 2; kk++) {
            const uint32_t ko = stg + kk * 32;
            uint32_t a_[4][4];
            #pragma unroll
            for (int mi = 0; mi < 4; mi++)
                LDMX4(a_[mi], aBb[mi] + ko);
            #pragma unroll
            for (int p = 0; p < 2; p++) {
                uint32_t b_[4];
                LDMX4(b_, bBb[p] + ko);
                #pragma unroll
                for (int q = 0; q < 2; q++) {
                    const int ni = p * 2 + q;
                    #pragma unroll
                    for (int mi = 0; mi < 4; mi++)
                        MMAH(acc[mi][ni], a_[mi][0], a_[mi][1], a_[mi][2], a_[mi][3], b_[2*q], b_[2*q+1]);
                }
            }
        }
        __syncthreads();
    }

    #pragma unroll
    for (int mi = 0; mi < 4; mi++) {
        int row0 = bm * 128 + wm * 64 + mi * 16 + gq;
        int b0_ = row0 >> 9,       s0_ = row0 & 511;
        int b1_ = (row0 + 8) >> 9, s1_ = (row0 + 8) & 511;
        #pragma unroll
        for (int ni = 0; ni < 4; ni++) {
            int col = col0 + wn * 32 + ni * 8 + tg * 2;
            float2 bb = {bg[col], bg[col + 1]};
            *(float2*)&g_xg[g][s0_][b0_][col] = make_float2(acc[mi][ni][0] + bb.x, acc[mi][ni][1] + bb.y);
            *(float2*)&g_xg[g][s1_][b1_][col] = make_float2(acc[mi][ni][2] + bb.x, acc[mi][ni][3] + bb.y);
        }
    }
}

// ---------------------------------------------------------------------------
// K2: persistent fp16 HMMA scan (identical to round 11 — at its sync floor).
// ---------------------------------------------------------------------------
#define SPITCH 264
#define OFF_U  0
#define OFF_H  (96 * SPITCH * 2)                 // 50688
#define SMEM_SCAN (OFF_H + 64 * SPITCH * 2)      // 84480

__global__ __launch_bounds__(NTHR_SCAN) void k_scan(
    const float* __restrict__ Uf, const float* __restrict__ Uo, const float* __restrict__ Uc,
    float* __restrict__ out)
{
    extern __shared__ char smem[];
    uint16_t* Usm = (uint16_t*)(smem + OFF_U);     // [urow 0..95][SPITCH]

    const int cta  = blockIdx.x;          // 0..127
    const int ct   = cta >> 2;            // coltile 0..31 (32 cols)
    const int ks   = cta & 3;             // ksplit (K=256)
    const int kbeg = ks * KCHUNK;
    const int colbase = ct * 32;

    const int tid  = threadIdx.x;
    const int wid  = tid >> 5;
    const int lane = tid & 31;
    const int gq   = lane >> 2;
    const int tg   = lane & 3;
    const int mi   = wid & 3;             // 16-batch-row block
    const int nj   = wid >> 2;            // 48-urow block (0..1)
    const int gtid = cta * NTHR_SCAN + tid;

    // ---- convert U slice (3 gates x 32 cols x 256 k) to fp16 SMEM ----
    const float* Usrc[3] = {Uf, Uo, Uc};
    for (int q = tid; q < 96 * 64; q += NTHR_SCAN) {   // float4 slots
        int urow = q >> 6;
        int g    = urow >> 5;
        int r    = urow & 31;
        int k    = (q & 63) << 2;
        float4 u = *(const float4*)(Usrc[g] + (size_t)(colbase + r) * HH + kbeg + k);
        __half2 p0 = __floats2half2_rn(u.x, u.y);
        __half2 p1 = __floats2half2_rn(u.z, u.w);
        *(__half2*)&Usm[urow * SPITCH + k]     = p0;
        *(__half2*)&Usm[urow * SPITCH + k + 2] = p1;
    }

    // ---- zero h (graph replays must not inherit state) ----
    for (int i = gtid; i < BB * HH; i += SCAN_THREADS)
        g_hf[i] = __ushort_as_half((unsigned short)0);

    // ---- per-thread ldmatrix base addresses ----
    const uint32_t sb = smem_u32(smem);
    const int arow = mi * 16 + (lane & 7) + ((lane >> 3) & 1) * 8;
    const int akc  = ((lane >> 4) & 1) * 8;
    const uint32_t aB = sb + OFF_H + (arow * SPITCH + akc) * 2;
    const int brow = (lane & 7) + ((lane >> 4) & 1) * 8;
    const int bkc  = ((lane >> 3) & 1) * 8;
    uint32_t bB[3];
    #pragma unroll
    for (int j = 0; j < 3; j++) {
        int r = nj * 48 + j * 16 + brow;
        bB[j] = sb + OFF_U + (r * SPITCH + bkc) * 2;
    }

    const int b0_ = mi * 16 + gq;
    const int b1_ = b0_ + 8;

    // staging: this warp owns h-rows [rowbase, rowbase+8)
    const int rowbase = mi * 16 + nj * 8;

    // phase B: CTA (ct,ks) owns cols [colbase+ks*8, +8) x all 64 b; c in regs
    const int pb_b   = tid >> 2;
    const int pb_col = colbase + ks * 8 + (tid & 3) * 2;
    float cc0 = 0.0f, cc1 = 0.0f;

    unsigned gen = 1;
    grid_sync(gen++);

    for (int t = 0; t < SS; t++) {
        // ---- stage this pair's h rows (8 rows x 256 fp16) ----
        #pragma unroll
        for (int i = 0; i < 8; i++) {
            int row = rowbase + i;
            const char* sh = (const char*)g_hf + (size_t)row * (HH * 2) + kbeg * 2;
            *(uint4*)(smem + OFF_H + row * (SPITCH * 2) + lane * 16) =
                ((const uint4*)sh)[lane];
        }
        BAR_SYNC(mi + 1, 64);             // pair barrier: warps mi and mi+4

        // ---- HMMA: D[16 b][48 urows] per warp, K=256, single fp16 term ----
        float acc[6][4] = {};
        #pragma unroll 4
        for (int kk = 0; kk < 16; kk++) {
            const uint32_t ko = kk * 32;
            uint32_t a[4];
            LDMX4(a, aB + ko);
            #pragma unroll
            for (int j = 0; j < 3; j++) {
                uint32_t b[4];
                LDMX4(b, bB[j] + ko);
                MMAH(acc[j*2],   a[0], a[1], a[2], a[3], b[0], b[1]);
                MMAH(acc[j*2+1], a[0], a[1], a[2], a[3], b[2], b[3]);
            }
        }

        // ---- write partials: urow -> (gate, col) ----
        #pragma unroll
        for (int idx = 0; idx < 6; idx++) {
            int n    = nj * 48 + idx * 8 + tg * 2;
            int g    = n >> 5;
            int col  = colbase + (n & 31);
            *(float2*)&g_part[ks][g][b0_][col] = make_float2(acc[idx][0], acc[idx][1]);
            *(float2*)&g_part[ks][g][b1_][col] = make_float2(acc[idx][2], acc[idx][3]);
        }
        __syncthreads();                   // all partial stores done CTA-wide
        if (tid == 0) red_rel_add(&g_flag[ct], 1u);

        // ---- prefetch phase-B gate pre-activations (fly during flag wait)
        float2 xf = *(const float2*)&g_xg[0][t][pb_b][pb_col];
        float2 xo = *(const float2*)&g_xg[1][t][pb_b][pb_col];
        float2 xc = *(const float2*)&g_xg[2][t][pb_b][pb_col];

        // ---- group-local wait: all 4 ksplit CTAs of this coltile done ----
        if (tid == 0) {
            while (ld_acq(&g_flag[ct]) < 4u * (unsigned)(t + 1)) { }
        }
        __syncthreads();

        // ---- phase B: reduce 4 ksplits x 3 gates, update c, write h ----
        {
            float pf0 = xf.x, pf1 = xf.y;
            float po0 = xo.x, po1 = xo.y;
            float pc0 = xc.x, pc1 = xc.y;
            #pragma unroll
            for (int k = 0; k < KSPLIT; k++) {
                float2 v;
                v = *(const float2*)&g_part[k][0][pb_b][pb_col];
                pf0 += v.x; pf1 += v.y;
                v = *(const float2*)&g_part[k][1][pb_b][pb_col];
                po0 += v.x; po1 += v.y;
                v = *(const float2*)&g_part[k][2][pb_b][pb_col];
                pc0 += v.x; pc1 += v.y;
            }
            cc0 = fast_sigmoid(pf0) * cc0 + fast_tanh(pc0);
            cc1 = fast_sigmoid(pf1) * cc1 + fast_tanh(pc1);
            float h0 = fast_sigmoid(po0) * cc0;
            float h1 = fast_sigmoid(po1) * cc1;

            *(__half2*)&g_hf[pb_b * HH + pb_col] = __floats2half2_rn(h0, h1);

            *(float2*)&out[((size_t)pb_b * SS + t) * HH + pb_col] = make_float2(h0, h1);
            if (t == SS - 1) {
                float* o2 = out + (size_t)BB * SS * HH;
                *(float2*)&o2[pb_b * HH + pb_col] = make_float2(h0, h1);
                float* o3 = o2 + BB * HH;
                *(float2*)&o3[pb_b * HH + pb_col] = make_float2(cc0, cc1);
            }
        }

        grid_sync(gen++);                  // single global barrier per step
    }
}

extern "C" void kernel_launch(void* const* d_in, const int* in_sizes, int n_in,
                              void* d_out, int out_size) {
    const float* X  = (const float*)d_in[0];
    const float* Wf = (const float*)d_in[1];
    const float* Uf = (const float*)d_in[2];
    const float* bf = (const float*)d_in[3];
    // d_in[4..6] = W_i/U_i/b_i: gate i is computed-but-unused in the reference.
    const float* Wo = (const float*)d_in[7];
    const float* Uo = (const float*)d_in[8];
    const float* bo = (const float*)d_in[9];
    const float* Wc = (const float*)d_in[10];
    const float* Uc = (const float*)d_in[11];
    const float* bc = (const float*)d_in[12];
    float* out = (float*)d_out;

    cudaFuncSetAttribute(k_ingemm, cudaFuncAttributeMaxDynamicSharedMemorySize, SMEM_IN);
    cudaFuncSetAttribute(k_scan, cudaFuncAttributeMaxDynamicSharedMemorySize, SMEM_SCAN);

    k_reset<<<1, 32>>>();
    k_conv<<<4096, 256>>>(X,  0, (BB * SS * II) / 4);
    k_conv<<<1024, 256>>>(Wf, 1, (HH * II) / 4);
    k_conv<<<1024, 256>>>(Wo, 2, (HH * II) / 4);
    k_conv<<<1024, 256>>>(Wc, 3, (HH * II) / 4);
    k_ingemm<<<dim3(256, 24), 256, SMEM_IN>>>(bf, bo, bc);
    k_scan<<<NCTA_SCAN, NTHR_SCAN, SMEM_SCAN>>>(Uf, Uo, Uc, out);
}